// round 10
// baseline (speedup 1.0000x reference)
#include <cuda_runtime.h>
#include <cuda_bf16.h>
#include <math.h>
#include <stdint.h>

// Problem constants: N=30000, E=480000, D=128, R=16, H=4, DH=32, L=3
#define MAXN 30000
#define MAXE 480000
#define D 128
#define R 16
#define NH 4
#define DH 32
#define NL 3
#define NKMAX (MAXN * (R + 1))

// ---------------- scratch ----------------------------------------------------
__device__ float g_hcat[(long)MAXN * (2 * D)];
__device__ float g_z[(long)MAXN * D];
__device__ float g_el[MAXN * NH];
__device__ float g_er[MAXN * NH];
__device__ float g_twsum;
__device__ int g_cnt[NKMAX];
__device__ int g_off[NKMAX + 1];
__device__ int g_cur[NKMAX];
__device__ int g_btot[512];
__device__ int g_buf[2 * MAXE];
// bf16 hi/lo activation buffer pairs (max K = 256)
__device__ __nv_bfloat16 g_ahi[(long)MAXN * 256];
__device__ __nv_bfloat16 g_alo[(long)MAXN * 256];
__device__ __nv_bfloat16 g_bhi[(long)MAXN * 256];
__device__ __nv_bfloat16 g_blo[(long)MAXN * 256];
// packed bf16-pair weights (rows of 128 words, column-permuted):
//   [0,3072): W_rel (3 x 16 x 64)  [3072,3264): W_loop (3x64) [3264,3456): W_gat (3x64)
//   [3456,3584): W_fuse            [3584,3648): W_gate
#define WPK_ROWS 3648
__device__ uint32_t g_wpk_hi[WPK_ROWS * 128];
__device__ uint32_t g_wpk_lo[WPK_ROWS * 128];

// ---------------- helpers ----------------------------------------------------
__device__ __forceinline__ void red_add_v2(float* p, float x, float y) {
    asm volatile("red.global.add.v2.f32 [%0], {%1, %2};"
                 :: "l"(p), "f"(x), "f"(y) : "memory");
}
__device__ __forceinline__ void red_add_v4(float* p, float x, float y, float z, float w) {
    asm volatile("red.global.add.v4.f32 [%0], {%1, %2, %3, %4};"
                 :: "l"(p), "f"(x), "f"(y), "f"(z), "f"(w) : "memory");
}
__device__ __forceinline__ void ldsm4(uint32_t r[4], uint32_t addr) {
    asm volatile("ldmatrix.sync.aligned.m8n8.x4.shared.b16 {%0,%1,%2,%3}, [%4];"
                 : "=r"(r[0]), "=r"(r[1]), "=r"(r[2]), "=r"(r[3]) : "r"(addr));
}
__device__ __forceinline__ void mma16816(float c[4], const uint32_t a[4], const uint32_t b[2]) {
    asm volatile("mma.sync.aligned.m16n8k16.row.col.f32.bf16.bf16.f32 "
                 "{%0,%1,%2,%3}, {%4,%5,%6,%7}, {%8,%9}, {%0,%1,%2,%3};"
                 : "+f"(c[0]), "+f"(c[1]), "+f"(c[2]), "+f"(c[3])
                 : "r"(a[0]), "r"(a[1]), "r"(a[2]), "r"(a[3]), "r"(b[0]), "r"(b[1]));
}
__device__ __forceinline__ void cp16(uint32_t dst, const void* src, bool pred) {
    int sz = pred ? 16 : 0;
    asm volatile("cp.async.cg.shared.global [%0], [%1], 16, %2;"
                 :: "r"(dst), "l"(src), "r"(sz));
}
__device__ __forceinline__ void cp_commit() { asm volatile("cp.async.commit_group;"); }
template <int NN> __device__ __forceinline__ void cp_wait() {
    asm volatile("cp.async.wait_group %0;" :: "n"(NN));
}

// convert 4 floats -> bf16 hi/lo pairs, store as 2x bf162 each
__device__ __forceinline__ void cvt4_store(float4 v, __nv_bfloat16* hi, __nv_bfloat16* lo) {
    __nv_bfloat162 H0, H1, L0, L1;
    H0.x = __float2bfloat16_rn(v.x); H0.y = __float2bfloat16_rn(v.y);
    H1.x = __float2bfloat16_rn(v.z); H1.y = __float2bfloat16_rn(v.w);
    L0.x = __float2bfloat16_rn(v.x - __bfloat162float(H0.x));
    L0.y = __float2bfloat16_rn(v.y - __bfloat162float(H0.y));
    L1.x = __float2bfloat16_rn(v.z - __bfloat162float(H1.x));
    L1.y = __float2bfloat16_rn(v.w - __bfloat162float(H1.y));
    ((__nv_bfloat162*)hi)[0] = H0; ((__nv_bfloat162*)hi)[1] = H1;
    ((__nv_bfloat162*)lo)[0] = L0; ((__nv_bfloat162*)lo)[1] = L1;
}

// ---------------- conversion kernels ------------------------------------------
__global__ void cvt_act_k(const float* __restrict__ x,
                          __nv_bfloat16* __restrict__ hi, __nv_bfloat16* __restrict__ lo,
                          int total4)
{
    int i = blockIdx.x * blockDim.x + threadIdx.x;
    if (i >= total4) return;
    float4 v = ((const float4*)x)[i];
    cvt4_store(v, hi + i * 4, lo + i * 4);
}

__global__ void cvt_wt_k(const float* __restrict__ W,
                         uint32_t* __restrict__ hi, uint32_t* __restrict__ lo, int k2max)
{
    int i = blockIdx.x * blockDim.x + threadIdx.x;
    if (i >= k2max * 128) return;
    int k2 = i >> 7, n = i & 127;
    float a = W[(2 * k2) * 128 + n];
    float b = W[(2 * k2 + 1) * 128 + n];
    __nv_bfloat16 ah = __float2bfloat16_rn(a), bh = __float2bfloat16_rn(b);
    __nv_bfloat162 H; H.x = ah; H.y = bh;
    __nv_bfloat162 Lw;
    Lw.x = __float2bfloat16_rn(a - __bfloat162float(ah));
    Lw.y = __float2bfloat16_rn(b - __bfloat162float(bh));
    int np = (n & ~31) | ((n & 7) << 2) | ((n >> 3) & 3);
    hi[k2 * 128 + np] = *(uint32_t*)&H;
    lo[k2 * 128 + np] = *(uint32_t*)&Lw;
}

// ---------------- CSR build ----------------------------------------------------
__global__ void zero_int_k(int* p, int n) {
    int i = blockIdx.x * blockDim.x + threadIdx.x;
    if (i < n) p[i] = 0;
}
__global__ void hist_k(const int* __restrict__ src, const int* __restrict__ dst,
                       const int* __restrict__ et, int* __restrict__ cnt, int E, int NR)
{
    int e = blockIdx.x * blockDim.x + threadIdx.x;
    if (e >= E) return;
    atomicAdd(&cnt[src[e] * R + et[e]], 1);
    atomicAdd(&cnt[NR + dst[e]], 1);
}
__global__ void scan1_k(const int* __restrict__ cnt, int* __restrict__ off,
                        int* __restrict__ btot, int n)
{
    __shared__ int ws[8];
    int t = threadIdx.x;
    int base = blockIdx.x * 2048 + t * 8;
    int v[8], s = 0;
#pragma unroll
    for (int i = 0; i < 8; i++) {
        int x = (base + i < n) ? cnt[base + i] : 0;
        v[i] = s; s += x;
    }
    int lane = t & 31, w = t >> 5;
    int inc = s;
#pragma unroll
    for (int o = 1; o < 32; o <<= 1) {
        int y = __shfl_up_sync(0xFFFFFFFFu, inc, o);
        if (lane >= o) inc += y;
    }
    if (lane == 31) ws[w] = inc;
    int texc = inc - s;
    __syncthreads();
    int wbase = 0;
#pragma unroll
    for (int i = 0; i < 8; i++) wbase += (i < w) ? ws[i] : 0;
#pragma unroll
    for (int i = 0; i < 8; i++)
        if (base + i < n) off[base + i] = wbase + texc + v[i];
    if (t == 255) btot[blockIdx.x] = wbase + inc;
}
__global__ void scan2_k(int* btot, int nb) {
    __shared__ int ws[8];
    int t = threadIdx.x;
    int xv = (t < nb) ? btot[t] : 0;
    int lane = t & 31, w = t >> 5;
    int inc = xv;
#pragma unroll
    for (int o = 1; o < 32; o <<= 1) {
        int y = __shfl_up_sync(0xFFFFFFFFu, inc, o);
        if (lane >= o) inc += y;
    }
    if (lane == 31) ws[w] = inc;
    __syncthreads();
    int wbase = 0;
#pragma unroll
    for (int i = 0; i < 8; i++) wbase += (i < w) ? ws[i] : 0;
    if (t < nb) btot[t] = wbase + inc - xv;
}
__global__ void scan3_k(int* __restrict__ off, int* __restrict__ cur,
                        const int* __restrict__ btot, int n, int total)
{
    int i = blockIdx.x * blockDim.x + threadIdx.x;
    if (i < n) {
        int o = off[i] + btot[i >> 11];
        off[i] = o; cur[i] = o;
    }
    if (i == 0) off[n] = total;
}
__global__ void fill_k(const int* __restrict__ src, const int* __restrict__ dst,
                       const int* __restrict__ et, int* __restrict__ cur,
                       int* __restrict__ buf, int E, int NR)
{
    int e = blockIdx.x * blockDim.x + threadIdx.x;
    if (e >= E) return;
    int s = src[e], d = dst[e];
    int p1 = atomicAdd(&cur[s * R + et[e]], 1);
    buf[p1] = d;
    int p2 = atomicAdd(&cur[NR + d], 1);
    buf[p2] = s;
}

// hcat[:,0:128] = b_rel (rel scatter and W_loop epilogue both red_add onto it)
__global__ void init_base_k(float* __restrict__ hcat, const float* __restrict__ brel, int n) {
    int idx = blockIdx.x * blockDim.x + threadIdx.x;
    if (idx < n * D) {
        int node = idx >> 7, d = idx & 127;
        hcat[(long)node * 256 + d] = brel[d];
    }
}

// ---------------- bf16x3 tensor-core GEMMs -----------------------------------
#define AS_BUF 8192
#define BS_BUF 8704
#define OFF_AHI 0
#define OFF_ALO (2 * AS_BUF)
#define OFF_B5  (4 * AS_BUF)
#define SMEM_STD (4 * AS_BUF + 4 * BS_BUF)   // 67584

// ===== mega kernel: per layer, grid (MB, 18) =====
//  y==0: hcat[:,0:128] += X @ W_loop   (red_add; base pre-set to b_rel)
//  y==1: z = X @ W_gat  (+ inline el/er)
//  y>=2: rel r=y-2: CSR scatter of X @ W_rel[r] via paired red.v4
__global__ __launch_bounds__(512)
void mega_k(const __nv_bfloat16* __restrict__ Ahi, const __nv_bfloat16* __restrict__ Alo,
            const uint32_t* __restrict__ wrel_hi, const uint32_t* __restrict__ wrel_lo,
            const uint32_t* __restrict__ wloop_hi, const uint32_t* __restrict__ wloop_lo,
            const uint32_t* __restrict__ wgat_hi, const uint32_t* __restrict__ wgat_lo,
            float* __restrict__ hcat, float* __restrict__ zout,
            float* __restrict__ el, float* __restrict__ er,
            const float* __restrict__ attnl, const float* __restrict__ attnr,
            const int* __restrict__ csr_off, const int* __restrict__ csr_buf,
            int M)
{
    extern __shared__ char sm[];
    const uint32_t smB = (uint32_t)__cvta_generic_to_shared(sm);

    const int y = blockIdx.y;
    const uint32_t *BhY, *BlY;
    if (y == 0)      { BhY = wloop_hi; BlY = wloop_lo; }
    else if (y == 1) { BhY = wgat_hi;  BlY = wgat_lo;  }
    else             { BhY = wrel_hi + (long)(y - 2) * (64 * 128);
                       BlY = wrel_lo + (long)(y - 2) * (64 * 128); }

    const int m0   = blockIdx.x * 128;
    const int tid  = threadIdx.x;
    const int lane = tid & 31;
    const int wid  = tid >> 5;
    const int grp  = lane >> 2;
    const int tig  = lane & 3;
    const int wm   = (wid >> 2) * 32;
    const int wn   = (wid & 3) * 32;

    const int aRow = tid >> 2;
    const int aC   = tid & 3;
    const int aSC  = aC ^ ((aRow >> 1) & 3);
    const int gmA  = m0 + aRow;
    const bool aOk = gmA < M;
    const long aSrcOff = (long)(aOk ? gmA : 0) * D + aC * 8;
    const uint32_t aDst = aRow * 64 + aSC * 16;
    const int bRow = tid >> 5;
    const int bC   = tid & 31;
    const uint32_t bDst = bRow * 544 + bC * 16;
    const int bSrcOff = bRow * 128 + bC * 4;

    auto issue = [&](int k0, int b) {
        cp16(smB + OFF_AHI + b * AS_BUF + aDst, Ahi + aSrcOff + k0, aOk);
        cp16(smB + OFF_ALO + b * AS_BUF + aDst, Alo + aSrcOff + k0, aOk);
        cp16(smB + OFF_B5 + (b * 2 + 0) * BS_BUF + bDst, BhY + (k0 >> 1) * 128 + bSrcOff, true);
        cp16(smB + OFF_B5 + (b * 2 + 1) * BS_BUF + bDst, BlY + (k0 >> 1) * 128 + bSrcOff, true);
        cp_commit();
    };

    float acc[2][4][4];
#pragma unroll
    for (int i = 0; i < 2; i++)
#pragma unroll
        for (int j = 0; j < 4; j++)
#pragma unroll
            for (int k = 0; k < 4; k++) acc[i][j][k] = 0.f;

    const int arow_l  = wm + (lane & 15);
    const int aShift  = (arow_l >> 1) & 3;
    const int aChunk0 = lane >> 4;
    const uint32_t aRowByte = arow_l * 64;

    issue(0, 0);
#pragma unroll 1
    for (int c = 0; c < 4; c++) {
        const int b = c & 1;
        if (c + 1 < 4) issue((c + 1) << 5, b ^ 1);
        if (c + 1 < 4) cp_wait<1>(); else cp_wait<0>();
        __syncthreads();

        const char* bsH = sm + OFF_B5 + (b * 2 + 0) * BS_BUF;
        const char* bsL = sm + OFF_B5 + (b * 2 + 1) * BS_BUF;
#pragma unroll
        for (int kc = 0; kc < 2; kc++) {
            uint32_t ah[2][4], al[2][4];
#pragma unroll
            for (int mt = 0; mt < 2; mt++) {
                const int sc = ((kc * 2 + aChunk0) ^ aShift) * 16;
                uint32_t off = aRowByte + mt * 1024 + sc;
                ldsm4(ah[mt], smB + OFF_AHI + b * AS_BUF + off);
                ldsm4(al[mt], smB + OFF_ALO + b * AS_BUF + off);
            }
            const int r0 = kc * 8 + tig;
            const uint32_t bo0 = (uint32_t)((r0 * 136 + wn + grp * 4) << 2);
            const uint32_t bo1 = (uint32_t)(((r0 + 4) * 136 + wn + grp * 4) << 2);
            uint4 h0 = *(const uint4*)(bsH + bo0);
            uint4 h1 = *(const uint4*)(bsH + bo1);
            uint4 l0 = *(const uint4*)(bsL + bo0);
            uint4 l1 = *(const uint4*)(bsL + bo1);
            uint32_t bh[4][2], bl[4][2];
            bh[0][0] = h0.x; bh[1][0] = h0.y; bh[2][0] = h0.z; bh[3][0] = h0.w;
            bh[0][1] = h1.x; bh[1][1] = h1.y; bh[2][1] = h1.z; bh[3][1] = h1.w;
            bl[0][0] = l0.x; bl[1][0] = l0.y; bl[2][0] = l0.z; bl[3][0] = l0.w;
            bl[0][1] = l1.x; bl[1][1] = l1.y; bl[2][1] = l1.z; bl[3][1] = l1.w;
#pragma unroll
            for (int mt = 0; mt < 2; mt++)
#pragma unroll
                for (int nt = 0; nt < 4; nt++) {
                    mma16816(acc[mt][nt], ah[mt], bh[nt]);
                    mma16816(acc[mt][nt], al[mt], bh[nt]);
                    mma16816(acc[mt][nt], ah[mt], bl[nt]);
                }
        }
        __syncthreads();
    }

    // ---------------- epilogues ----------------
    if (y == 0) {
        // hcat[:,0:128] += X@W_loop (atomic; base = b_rel, rel scatter adds too)
#pragma unroll
        for (int mt = 0; mt < 2; mt++)
#pragma unroll
            for (int nt = 0; nt < 4; nt++) {
                const int n = wn + nt * 8 + 2 * tig;
#pragma unroll
                for (int half = 0; half < 2; half++) {
                    const int gm = m0 + wm + mt * 16 + grp + half * 8;
                    if (gm >= M) continue;
                    red_add_v2(hcat + (long)gm * 256 + n,
                               acc[mt][nt][half * 2 + 0], acc[mt][nt][half * 2 + 1]);
                }
            }
        return;
    }

    if (y == 1) {
        // z store + inline el/er (warp owns head h = wid&3)
        const int h = wid & 3;
#pragma unroll
        for (int mt = 0; mt < 2; mt++)
#pragma unroll
            for (int half = 0; half < 2; half++) {
                const int gm = m0 + wm + mt * 16 + grp + half * 8;
                const bool ok = gm < M;
                float elp = 0.f, erp = 0.f;
#pragma unroll
                for (int nt = 0; nt < 4; nt++) {
                    const int n = wn + nt * 8 + 2 * tig;
                    float v0 = acc[mt][nt][half * 2 + 0];
                    float v1 = acc[mt][nt][half * 2 + 1];
                    if (ok) {
                        float2 o; o.x = v0; o.y = v1;
                        *(float2*)(zout + (long)gm * 128 + n) = o;
                    }
                    const int dh = nt * 8 + 2 * tig;
                    elp += v0 * attnl[h * 32 + dh] + v1 * attnl[h * 32 + dh + 1];
                    erp += v0 * attnr[h * 32 + dh] + v1 * attnr[h * 32 + dh + 1];
                }
                elp += __shfl_xor_sync(0xFFFFFFFFu, elp, 1);
                elp += __shfl_xor_sync(0xFFFFFFFFu, elp, 2);
                erp += __shfl_xor_sync(0xFFFFFFFFu, erp, 1);
                erp += __shfl_xor_sync(0xFFFFFFFFu, erp, 2);
                if (ok && tig == 0) {
                    el[gm * NH + h] = elp;
                    er[gm * NH + h] = erp;
                }
            }
        return;
    }

    // y >= 2: rel scatter via paired red.v4
    const int rY  = y - 2;
    const int g4  = (tig >> 1) * 4;
    const int ntb = (tig & 1) * 2;
#pragma unroll
    for (int mt = 0; mt < 2; mt++)
#pragma unroll
        for (int half = 0; half < 2; half++) {
            const int gm = m0 + wm + mt * 16 + grp + half * 8;
            float q[4][4];
#pragma unroll
            for (int nt = 0; nt < 4; nt++) {
                float v0 = acc[mt][nt][half * 2 + 0];
                float v1 = acc[mt][nt][half * 2 + 1];
                float o0 = __shfl_xor_sync(0xFFFFFFFFu, v0, 1);
                float o1 = __shfl_xor_sync(0xFFFFFFFFu, v1, 1);
                if ((tig & 1) == 0) { q[nt][0] = v0; q[nt][1] = v1; q[nt][2] = o0; q[nt][3] = o1; }
                else                { q[nt][0] = o0; q[nt][1] = o1; q[nt][2] = v0; q[nt][3] = v1; }
            }
            if (gm >= M) continue;
            const int key = gm * R + rY;
            const int e0 = csr_off[key], e1 = csr_off[key + 1];
            for (int e = e0; e < e1; e++) {
                const int d = csr_buf[e];
                float* basep = hcat + (long)d * 256 + wn + g4;
                red_add_v4(basep + ntb * 8,
                           q[ntb][0], q[ntb][1], q[ntb][2], q[ntb][3]);
                red_add_v4(basep + (ntb + 1) * 8,
                           q[ntb + 1][0], q[ntb + 1][1], q[ntb + 1][2], q[ntb + 1][3]);
            }
        }
}

// ===== standard GEMM (fuse/gate): MODE 1 bias+relu->fp32 | 2 bias+relu->bf16 |
//                                   3 bias->fp32+bf16 | 4 temporal gate->bf16 =====
template <int MODE>
__global__ __launch_bounds__(512)
void bf_gemm(const __nv_bfloat16* __restrict__ Ahi, const __nv_bfloat16* __restrict__ Alo,
             int lda,
             const uint32_t* __restrict__ Bhi, const uint32_t* __restrict__ Blo,
             float* __restrict__ C, int ldc,
             __nv_bfloat16* __restrict__ obhi, __nv_bfloat16* __restrict__ oblo,
             int M, int K,
             const float* __restrict__ bias,
             const float* __restrict__ hcsrc, const float* __restrict__ gate_wlast,
             const float* __restrict__ tw_sum, float invE)
{
    extern __shared__ char sm[];
    const uint32_t smB = (uint32_t)__cvta_generic_to_shared(sm);

    const int m0   = blockIdx.x * 128;
    const int tid  = threadIdx.x;
    const int lane = tid & 31;
    const int wid  = tid >> 5;
    const int grp  = lane >> 2;
    const int tig  = lane & 3;
    const int wm   = (wid >> 2) * 32;
    const int wn   = (wid & 3) * 32;

    const int aRow = tid >> 2;
    const int aC   = tid & 3;
    const int aSC  = aC ^ ((aRow >> 1) & 3);
    const int gmA  = m0 + aRow;
    const bool aOk = gmA < M;
    const long aSrcOff = (long)(aOk ? gmA : 0) * lda + aC * 8;
    const uint32_t aDst = aRow * 64 + aSC * 16;
    const int bRow = tid >> 5;
    const int bC   = tid & 31;
    const uint32_t bDst = bRow * 544 + bC * 16;
    const int bSrcOff = bRow * 128 + bC * 4;

    auto issue = [&](int k0, int b) {
        cp16(smB + OFF_AHI + b * AS_BUF + aDst, Ahi + aSrcOff + k0, aOk);
        cp16(smB + OFF_ALO + b * AS_BUF + aDst, Alo + aSrcOff + k0, aOk);
        cp16(smB + OFF_B5 + (b * 2 + 0) * BS_BUF + bDst, Bhi + (k0 >> 1) * 128 + bSrcOff, true);
        cp16(smB + OFF_B5 + (b * 2 + 1) * BS_BUF + bDst, Blo + (k0 >> 1) * 128 + bSrcOff, true);
        cp_commit();
    };

    float acc[2][4][4];
#pragma unroll
    for (int i = 0; i < 2; i++)
#pragma unroll
        for (int j = 0; j < 4; j++)
#pragma unroll
            for (int k = 0; k < 4; k++) acc[i][j][k] = 0.f;

    const int arow_l  = wm + (lane & 15);
    const int aShift  = (arow_l >> 1) & 3;
    const int aChunk0 = lane >> 4;
    const uint32_t aRowByte = arow_l * 64;

    const int nch = K >> 5;
    issue(0, 0);

    for (int c = 0; c < nch; c++) {
        const int b = c & 1;
        if (c + 1 < nch) issue((c + 1) << 5, b ^ 1);
        if (c + 1 < nch) cp_wait<1>(); else cp_wait<0>();
        __syncthreads();

        const char* bsH = sm + OFF_B5 + (b * 2 + 0) * BS_BUF;
        const char* bsL = sm + OFF_B5 + (b * 2 + 1) * BS_BUF;
#pragma unroll
        for (int kc = 0; kc < 2; kc++) {
            uint32_t ah[2][4], al[2][4];
#pragma unroll
            for (int mt = 0; mt < 2; mt++) {
                const int sc = ((kc * 2 + aChunk0) ^ aShift) * 16;
                uint32_t off = aRowByte + mt * 1024 + sc;
                ldsm4(ah[mt], smB + OFF_AHI + b * AS_BUF + off);
                ldsm4(al[mt], smB + OFF_ALO + b * AS_BUF + off);
            }
            const int r0 = kc * 8 + tig;
            const uint32_t bo0 = (uint32_t)((r0 * 136 + wn + grp * 4) << 2);
            const uint32_t bo1 = (uint32_t)(((r0 + 4) * 136 + wn + grp * 4) << 2);
            uint4 h0 = *(const uint4*)(bsH + bo0);
            uint4 h1 = *(const uint4*)(bsH + bo1);
            uint4 l0 = *(const uint4*)(bsL + bo0);
            uint4 l1 = *(const uint4*)(bsL + bo1);
            uint32_t bh[4][2], bl[4][2];
            bh[0][0] = h0.x; bh[1][0] = h0.y; bh[2][0] = h0.z; bh[3][0] = h0.w;
            bh[0][1] = h1.x; bh[1][1] = h1.y; bh[2][1] = h1.z; bh[3][1] = h1.w;
            bl[0][0] = l0.x; bl[1][0] = l0.y; bl[2][0] = l0.z; bl[3][0] = l0.w;
            bl[0][1] = l1.x; bl[1][1] = l1.y; bl[2][1] = l1.z; bl[3][1] = l1.w;
#pragma unroll
            for (int mt = 0; mt < 2; mt++)
#pragma unroll
                for (int nt = 0; nt < 4; nt++) {
                    mma16816(acc[mt][nt], ah[mt], bh[nt]);
                    mma16816(acc[mt][nt], al[mt], bh[nt]);
                    mma16816(acc[mt][nt], ah[mt], bl[nt]);
                }
        }
        __syncthreads();
    }

    float twm = 0.0f;
    if (MODE == 4) twm = tw_sum[0] * invE;

#pragma unroll
    for (int mt = 0; mt < 2; mt++)
#pragma unroll
        for (int nt = 0; nt < 4; nt++) {
            const int n = wn + nt * 8 + 2 * tig;
#pragma unroll
            for (int half = 0; half < 2; half++) {
                const int gm = m0 + wm + mt * 16 + grp + half * 8;
                if (gm >= M) continue;
                float v0 = acc[mt][nt][half * 2 + 0];
                float v1 = acc[mt][nt][half * 2 + 1];
                if (bias) { v0 += bias[n]; v1 += bias[n + 1]; }
                if (MODE == 1 || MODE == 2) { v0 = fmaxf(v0, 0.f); v1 = fmaxf(v1, 0.f); }
                if (MODE == 4) {
                    float g0 = v0 + twm * gate_wlast[n];
                    float g1 = v1 + twm * gate_wlast[n + 1];
                    g0 = 1.0f / (1.0f + expf(-g0));
                    g1 = 1.0f / (1.0f + expf(-g1));
                    float2 hc = *(const float2*)(hcsrc + (long)gm * 128 + n);
                    v0 = fmaxf(hc.x * g0, 0.f);
                    v1 = fmaxf(hc.y * g1, 0.f);
                }
                if (MODE == 1 || MODE == 3) {
                    float2 o; o.x = v0; o.y = v1;
                    *(float2*)(C + (long)gm * ldc + n) = o;
                }
                if (MODE == 2 || MODE == 3 || MODE == 4) {
                    __nv_bfloat162 H, Lw;
                    H.x = __float2bfloat16_rn(v0);
                    H.y = __float2bfloat16_rn(v1);
                    Lw.x = __float2bfloat16_rn(v0 - __bfloat162float(H.x));
                    Lw.y = __float2bfloat16_rn(v1 - __bfloat162float(H.y));
                    *(__nv_bfloat162*)(obhi + (long)gm * 128 + n) = H;
                    *(__nv_bfloat162*)(oblo + (long)gm * 128 + n) = Lw;
                }
            }
        }
}

// ---------------- GAT gather + fused bf16 conversion of full hcat row ------------
__global__ void gat_cvt_k(const int* __restrict__ off, const int* __restrict__ buf,
                          const float* __restrict__ el, const float* __restrict__ er,
                          const float* __restrict__ z, const float* __restrict__ bgat,
                          const float* __restrict__ hcat,
                          __nv_bfloat16* __restrict__ obhi, __nv_bfloat16* __restrict__ oblo,
                          int n, int NR)
{
    int node = (blockIdx.x * blockDim.x + threadIdx.x) >> 5;
    if (node >= n) return;
    int lane = threadIdx.x & 31;
    int d0 = lane * 4;
    int head = lane >> 3;

    // 1) convert rel half hcat[node, 0:128] -> bf16 hi/lo at cols [0,128)
    float4 base = *(const float4*)(hcat + (long)node * 256 + d0);
    cvt4_store(base, obhi + (long)node * 256 + d0, oblo + (long)node * 256 + d0);

    // 2) GAT gather (atomic-free) -> bf16 hi/lo at cols [128,256) (never touches fp32 hcat)
    int e0 = off[NR + node], e1 = off[NR + node + 1];
    float erv = er[node * NH + head];
    float ax0 = 0.f, ay0 = 0.f, az0 = 0.f, aw0 = 0.f, sx0 = 0.f;
    float ax1 = 0.f, ay1 = 0.f, az1 = 0.f, aw1 = 0.f, sx1 = 0.f;
    int j = e0;
    for (; j + 1 < e1; j += 2) {
        int s0 = buf[j], s1 = buf[j + 1];
        float v0 = el[s0 * NH + head] + erv;
        float v1 = el[s1 * NH + head] + erv;
        v0 = (v0 >= 0.f) ? v0 : 0.2f * v0;
        v1 = (v1 >= 0.f) ? v1 : 0.2f * v1;
        float ex0 = __expf(v0), ex1 = __expf(v1);
        float4 z0 = *(const float4*)(z + (long)s0 * 128 + d0);
        float4 z1 = *(const float4*)(z + (long)s1 * 128 + d0);
        sx0 += ex0; sx1 += ex1;
        ax0 = fmaf(ex0, z0.x, ax0); ay0 = fmaf(ex0, z0.y, ay0);
        az0 = fmaf(ex0, z0.z, az0); aw0 = fmaf(ex0, z0.w, aw0);
        ax1 = fmaf(ex1, z1.x, ax1); ay1 = fmaf(ex1, z1.y, ay1);
        az1 = fmaf(ex1, z1.z, az1); aw1 = fmaf(ex1, z1.w, aw1);
    }
    if (j < e1) {
        int s0 = buf[j];
        float v0 = el[s0 * NH + head] + erv;
        v0 = (v0 >= 0.f) ? v0 : 0.2f * v0;
        float ex0 = __expf(v0);
        float4 z0 = *(const float4*)(z + (long)s0 * 128 + d0);
        sx0 += ex0;
        ax0 = fmaf(ex0, z0.x, ax0); ay0 = fmaf(ex0, z0.y, ay0);
        az0 = fmaf(ex0, z0.z, az0); aw0 = fmaf(ex0, z0.w, aw0);
    }
    float sx = sx0 + sx1;
    float inv = (e1 > e0) ? (1.0f / sx) : 0.0f;
    float4 bg = *(const float4*)(bgat + d0);
    float4 o;
    o.x = fmaf(ax0 + ax1, inv, bg.x); o.y = fmaf(ay0 + ay1, inv, bg.y);
    o.z = fmaf(az0 + az1, inv, bg.z); o.w = fmaf(aw0 + aw1, inv, bg.w);
    cvt4_store(o, obhi + (long)node * 256 + 128 + d0, oblo + (long)node * 256 + 128 + d0);
}

// ---------------- misc ------------------------------------------------------------
__global__ void zero_scalar_k(float* p) { *p = 0.0f; }
__global__ void reduce_sum_k(const float* __restrict__ x, float* out, int n) {
    float s = 0.0f;
    for (int i = blockIdx.x * blockDim.x + threadIdx.x; i < n; i += gridDim.x * blockDim.x)
        s += x[i];
#pragma unroll
    for (int o = 16; o > 0; o >>= 1) s += __shfl_xor_sync(0xFFFFFFFFu, s, o);
    __shared__ float ws[8];
    if ((threadIdx.x & 31) == 0) ws[threadIdx.x >> 5] = s;
    __syncthreads();
    if (threadIdx.x < 32) {
        s = (threadIdx.x < (blockDim.x >> 5)) ? ws[threadIdx.x] : 0.0f;
#pragma unroll
        for (int o = 4; o > 0; o >>= 1) s += __shfl_xor_sync(0xFFFFFFFFu, s, o);
        if (threadIdx.x == 0) atomicAdd(out, s);
    }
}

// ---------------- launcher ----------------------------------------------------------
extern "C" void kernel_launch(void* const* d_in, const int* in_sizes, int n_in,
                              void* d_out, int out_size)
{
    const float* feat   = (const float*)d_in[0];
    const int*   src    = (const int*)  d_in[1];
    const int*   dst    = (const int*)  d_in[2];
    const int*   et     = (const int*)  d_in[3];
    const float* tw     = (const float*)d_in[4];
    const float* W_rel  = (const float*)d_in[5];
    const float* b_rel  = (const float*)d_in[6];
    const float* W_loop = (const float*)d_in[7];
    const float* W_gat  = (const float*)d_in[8];
    const float* attn_l = (const float*)d_in[9];
    const float* attn_r = (const float*)d_in[10];
    const float* b_gat  = (const float*)d_in[11];
    const float* W_fuse = (const float*)d_in[12];
    const float* b_fuse = (const float*)d_in[13];
    const float* W_gate = (const float*)d_in[14];
    const float* b_gate = (const float*)d_in[15];

    const int Nn = in_sizes[0] / D;
    const int E  = in_sizes[1];
    const int NR = Nn * R;
    const int NK = NR + Nn;

    cudaFuncSetAttribute(mega_k,     cudaFuncAttributeMaxDynamicSharedMemorySize, SMEM_STD);
    cudaFuncSetAttribute(bf_gemm<1>, cudaFuncAttributeMaxDynamicSharedMemorySize, SMEM_STD);
    cudaFuncSetAttribute(bf_gemm<2>, cudaFuncAttributeMaxDynamicSharedMemorySize, SMEM_STD);
    cudaFuncSetAttribute(bf_gemm<3>, cudaFuncAttributeMaxDynamicSharedMemorySize, SMEM_STD);
    cudaFuncSetAttribute(bf_gemm<4>, cudaFuncAttributeMaxDynamicSharedMemorySize, SMEM_STD);

    float *hcat, *z, *el, *er, *tws;
    int *cnt, *off, *cur, *btot, *buf;
    __nv_bfloat16 *Ahi, *Alo, *Bhi_a, *Blo_a;
    uint32_t *whi, *wlo;
    cudaGetSymbolAddress((void**)&hcat, g_hcat);
    cudaGetSymbolAddress((void**)&z,    g_z);
    cudaGetSymbolAddress((void**)&el,   g_el);
    cudaGetSymbolAddress((void**)&er,   g_er);
    cudaGetSymbolAddress((void**)&tws,  g_twsum);
    cudaGetSymbolAddress((void**)&cnt,  g_cnt);
    cudaGetSymbolAddress((void**)&off,  g_off);
    cudaGetSymbolAddress((void**)&cur,  g_cur);
    cudaGetSymbolAddress((void**)&btot, g_btot);
    cudaGetSymbolAddress((void**)&buf,  g_buf);
    cudaGetSymbolAddress((void**)&Ahi,  g_ahi);
    cudaGetSymbolAddress((void**)&Alo,  g_alo);
    cudaGetSymbolAddress((void**)&Bhi_a, g_bhi);
    cudaGetSymbolAddress((void**)&Blo_a, g_blo);
    cudaGetSymbolAddress((void**)&whi,  g_wpk_hi);
    cudaGetSymbolAddress((void**)&wlo,  g_wpk_lo);

    const int MB = (Nn + 127) / 128;
    const int TPB = 256;
    const int e_blocks      = (E + TPB - 1) / TPB;
    const int nk_blocks     = (NK + TPB - 1) / TPB;
    const int nb            = (NK + 2047) / 2048;
    const int gat_blocks    = (Nn + 7) / 8;
    const int nd_blocks     = (Nn * D + TPB - 1) / TPB;
    const int cvt128_blocks = (Nn * D / 4 + TPB - 1) / TPB;

    zero_scalar_k<<<1, 1>>>(tws);
    reduce_sum_k<<<256, 256>>>(tw, tws, E);

    // CSR build
    zero_int_k<<<nk_blocks, TPB>>>(cnt, NK);
    hist_k<<<e_blocks, TPB>>>(src, dst, et, cnt, E, NR);
    scan1_k<<<nb, 256>>>(cnt, off, btot, NK);
    scan2_k<<<1, 256>>>(btot, nb);
    scan3_k<<<nk_blocks, TPB>>>(off, cur, btot, NK, 2 * E);
    fill_k<<<e_blocks, TPB>>>(src, dst, et, cur, buf, E, NR);

    // weights (once)
    cvt_wt_k<<<(3072 * 128 + TPB - 1) / TPB, TPB>>>(W_rel,  whi,              wlo,              3072);
    cvt_wt_k<<<(192 * 128 + TPB - 1) / TPB, TPB>>>(W_loop, whi + 3072 * 128, wlo + 3072 * 128, 192);
    cvt_wt_k<<<(192 * 128 + TPB - 1) / TPB, TPB>>>(W_gat,  whi + 3264 * 128, wlo + 3264 * 128, 192);
    cvt_wt_k<<<(128 * 128 + TPB - 1) / TPB, TPB>>>(W_fuse, whi + 3456 * 128, wlo + 3456 * 128, 128);
    cvt_wt_k<<<(64 * 128 + TPB - 1) / TPB, TPB>>>(W_gate, whi + 3584 * 128, wlo + 3584 * 128, 64);

    // layer-0 activations
    cvt_act_k<<<cvt128_blocks, TPB>>>(feat, Ahi, Alo, Nn * D / 4);

    __nv_bfloat16 *cur_hi = Ahi, *cur_lo = Alo;
    __nv_bfloat16 *oth_hi = Bhi_a, *oth_lo = Blo_a;

    for (int l = 0; l < NL; l++) {
        const float* brel_l = b_rel  + l * D;
        const float* bgat_l = b_gat  + l * D;
        const float* al_l   = attn_l + l * NH * DH;
        const float* ar_l   = attn_r + l * NH * DH;
        const uint32_t* wrel_hi  = whi + (long)(l * 1024) * 128;
        const uint32_t* wrel_lo  = wlo + (long)(l * 1024) * 128;
        const uint32_t* wloop_hi = whi + (long)(3072 + l * 64) * 128;
        const uint32_t* wloop_lo = wlo + (long)(3072 + l * 64) * 128;
        const uint32_t* wgat_hi  = whi + (long)(3264 + l * 64) * 128;
        const uint32_t* wgat_lo  = wlo + (long)(3264 + l * 64) * 128;

        // 1) init hcat rel-half base to b_rel
        init_base_k<<<nd_blocks, TPB>>>(hcat, brel_l, Nn);

        // 2) mega GEMM: W_loop(red_add) + W_gat(z,el,er) + 16 rel GEMMs (CSR scatter)
        mega_k<<<dim3(MB, 18), 512, SMEM_STD>>>(
            cur_hi, cur_lo,
            wrel_hi, wrel_lo, wloop_hi, wloop_lo, wgat_hi, wgat_lo,
            hcat, z, el, er, al_l, ar_l,
            off, buf, Nn);

        // 3) GAT gather + fused bf16 conversion of both hcat halves -> oth buffers
        gat_cvt_k<<<gat_blocks, TPB>>>(off, buf, el, er, z, bgat_l, hcat,
                                       oth_hi, oth_lo, Nn, NR);

        // 4) fuse (+ gate at layer 0)
        if (l == 0) {
            bf_gemm<3><<<dim3(MB, 1), 512, SMEM_STD>>>(
                oth_hi, oth_lo, 2 * D, whi + (long)3456 * 128, wlo + (long)3456 * 128,
                z, D, cur_hi, cur_lo,
                Nn, 2 * D, b_fuse,
                nullptr, nullptr, nullptr, 0.f);
            bf_gemm<4><<<dim3(MB, 1), 512, SMEM_STD>>>(
                cur_hi, cur_lo, D, whi + (long)3584 * 128, wlo + (long)3584 * 128,
                nullptr, 0, oth_hi, oth_lo,
                Nn, D, b_gate,
                z, W_gate + (long)D * D, tws, 1.0f / (float)E);
            __nv_bfloat16* t;
            t = cur_hi; cur_hi = oth_hi; oth_hi = t;
            t = cur_lo; cur_lo = oth_lo; oth_lo = t;
        } else if (l < NL - 1) {
            bf_gemm<2><<<dim3(MB, 1), 512, SMEM_STD>>>(
                oth_hi, oth_lo, 2 * D, whi + (long)3456 * 128, wlo + (long)3456 * 128,
                nullptr, 0, cur_hi, cur_lo,
                Nn, 2 * D, b_fuse,
                nullptr, nullptr, nullptr, 0.f);
        } else {
            bf_gemm<1><<<dim3(MB, 1), 512, SMEM_STD>>>(
                oth_hi, oth_lo, 2 * D, whi + (long)3456 * 128, wlo + (long)3456 * 128,
                (float*)d_out, D, nullptr, nullptr,
                Nn, 2 * D, b_fuse,
                nullptr, nullptr, nullptr, 0.f);
        }
    }
}

// round 11
// speedup vs baseline: 1.0915x; 1.0915x over previous
#include <cuda_runtime.h>
#include <cuda_bf16.h>
#include <math.h>
#include <stdint.h>

// Problem constants: N=30000, E=480000, D=128, R=16, H=4, DH=32, L=3
#define MAXN 30000
#define MAXE 480000
#define D 128
#define R 16
#define NH 4
#define DH 32
#define NL 3
#define NKMAX (MAXN * (R + 1))

// ---------------- scratch ----------------------------------------------------
__device__ float g_hcat[(long)MAXN * (2 * D)];
__device__ float g_z[(long)MAXN * D];
__device__ float g_el[MAXN * NH];
__device__ float g_er[MAXN * NH];
__device__ float g_twsum;
__device__ int g_cnt[NKMAX];
__device__ int g_off[NKMAX + 1];
__device__ int g_cur[NKMAX];
__device__ int g_btot[512];
__device__ int g_buf[2 * MAXE];
// two bf16 hi/lo activation buffer pairs (max K = 256)
__device__ __nv_bfloat16 g_ahi[(long)MAXN * 256];
__device__ __nv_bfloat16 g_alo[(long)MAXN * 256];
__device__ __nv_bfloat16 g_bhi[(long)MAXN * 256];
__device__ __nv_bfloat16 g_blo[(long)MAXN * 256];
// packed bf16-pair weights (rows of 128 words, column-permuted):
//   [0,3072): W_rel (3 x 16 x 64)  [3072,3264): W_loop (3x64) [3264,3456): W_gat (3x64)
//   [3456,3584): W_fuse            [3584,3648): W_gate
#define WPK_ROWS 3648
__device__ uint32_t g_wpk_hi[WPK_ROWS * 128];
__device__ uint32_t g_wpk_lo[WPK_ROWS * 128];

// ---------------- helpers ----------------------------------------------------
__device__ __forceinline__ void red_add_v4(float* p, float x, float y, float z, float w) {
    asm volatile("red.global.add.v4.f32 [%0], {%1, %2, %3, %4};"
                 :: "l"(p), "f"(x), "f"(y), "f"(z), "f"(w) : "memory");
}
__device__ __forceinline__ void ldsm4(uint32_t r[4], uint32_t addr) {
    asm volatile("ldmatrix.sync.aligned.m8n8.x4.shared.b16 {%0,%1,%2,%3}, [%4];"
                 : "=r"(r[0]), "=r"(r[1]), "=r"(r[2]), "=r"(r[3]) : "r"(addr));
}
__device__ __forceinline__ void mma16816(float c[4], const uint32_t a[4], const uint32_t b[2]) {
    asm volatile("mma.sync.aligned.m16n8k16.row.col.f32.bf16.bf16.f32 "
                 "{%0,%1,%2,%3}, {%4,%5,%6,%7}, {%8,%9}, {%0,%1,%2,%3};"
                 : "+f"(c[0]), "+f"(c[1]), "+f"(c[2]), "+f"(c[3])
                 : "r"(a[0]), "r"(a[1]), "r"(a[2]), "r"(a[3]), "r"(b[0]), "r"(b[1]));
}
__device__ __forceinline__ void cp16(uint32_t dst, const void* src, bool pred) {
    int sz = pred ? 16 : 0;
    asm volatile("cp.async.cg.shared.global [%0], [%1], 16, %2;"
                 :: "r"(dst), "l"(src), "r"(sz));
}
__device__ __forceinline__ void cp_commit() { asm volatile("cp.async.commit_group;"); }
template <int NN> __device__ __forceinline__ void cp_wait() {
    asm volatile("cp.async.wait_group %0;" :: "n"(NN));
}
// convert 4 floats -> bf16 hi/lo pairs
__device__ __forceinline__ void cvt4_store(float4 v, __nv_bfloat16* hi, __nv_bfloat16* lo) {
    __nv_bfloat162 H0, H1, L0, L1;
    H0.x = __float2bfloat16_rn(v.x); H0.y = __float2bfloat16_rn(v.y);
    H1.x = __float2bfloat16_rn(v.z); H1.y = __float2bfloat16_rn(v.w);
    L0.x = __float2bfloat16_rn(v.x - __bfloat162float(H0.x));
    L0.y = __float2bfloat16_rn(v.y - __bfloat162float(H0.y));
    L1.x = __float2bfloat16_rn(v.z - __bfloat162float(H1.x));
    L1.y = __float2bfloat16_rn(v.w - __bfloat162float(H1.y));
    ((__nv_bfloat162*)hi)[0] = H0; ((__nv_bfloat162*)hi)[1] = H1;
    ((__nv_bfloat162*)lo)[0] = L0; ((__nv_bfloat162*)lo)[1] = L1;
}

// ---------------- conversion kernels ------------------------------------------
__global__ void cvt_act_k(const float* __restrict__ x,
                          __nv_bfloat16* __restrict__ hi, __nv_bfloat16* __restrict__ lo,
                          int total4)
{
    int i = blockIdx.x * blockDim.x + threadIdx.x;
    if (i >= total4) return;
    float4 v = ((const float4*)x)[i];
    cvt4_store(v, hi + i * 4, lo + i * 4);
}

__global__ void cvt_wt_k(const float* __restrict__ W,
                         uint32_t* __restrict__ hi, uint32_t* __restrict__ lo, int k2max)
{
    int i = blockIdx.x * blockDim.x + threadIdx.x;
    if (i >= k2max * 128) return;
    int k2 = i >> 7, n = i & 127;
    float a = W[(2 * k2) * 128 + n];
    float b = W[(2 * k2 + 1) * 128 + n];
    __nv_bfloat16 ah = __float2bfloat16_rn(a), bh = __float2bfloat16_rn(b);
    __nv_bfloat162 H; H.x = ah; H.y = bh;
    __nv_bfloat162 Lw;
    Lw.x = __float2bfloat16_rn(a - __bfloat162float(ah));
    Lw.y = __float2bfloat16_rn(b - __bfloat162float(bh));
    int np = (n & ~31) | ((n & 7) << 2) | ((n >> 3) & 3);
    hi[k2 * 128 + np] = *(uint32_t*)&H;
    lo[k2 * 128 + np] = *(uint32_t*)&Lw;
}

// ---------------- CSR build ----------------------------------------------------
__global__ void zero_int_k(int* p, int n) {
    int i = blockIdx.x * blockDim.x + threadIdx.x;
    if (i < n) p[i] = 0;
}
__global__ void hist_k(const int* __restrict__ src, const int* __restrict__ dst,
                       const int* __restrict__ et, int* __restrict__ cnt, int E, int NR)
{
    int e = blockIdx.x * blockDim.x + threadIdx.x;
    if (e >= E) return;
    atomicAdd(&cnt[src[e] * R + et[e]], 1);
    atomicAdd(&cnt[NR + dst[e]], 1);
}
__global__ void scan1_k(const int* __restrict__ cnt, int* __restrict__ off,
                        int* __restrict__ btot, int n)
{
    __shared__ int ws[8];
    int t = threadIdx.x;
    int base = blockIdx.x * 2048 + t * 8;
    int v[8], s = 0;
#pragma unroll
    for (int i = 0; i < 8; i++) {
        int x = (base + i < n) ? cnt[base + i] : 0;
        v[i] = s; s += x;
    }
    int lane = t & 31, w = t >> 5;
    int inc = s;
#pragma unroll
    for (int o = 1; o < 32; o <<= 1) {
        int y = __shfl_up_sync(0xFFFFFFFFu, inc, o);
        if (lane >= o) inc += y;
    }
    if (lane == 31) ws[w] = inc;
    int texc = inc - s;
    __syncthreads();
    int wbase = 0;
#pragma unroll
    for (int i = 0; i < 8; i++) wbase += (i < w) ? ws[i] : 0;
#pragma unroll
    for (int i = 0; i < 8; i++)
        if (base + i < n) off[base + i] = wbase + texc + v[i];
    if (t == 255) btot[blockIdx.x] = wbase + inc;
}
__global__ void scan2_k(int* btot, int nb) {
    __shared__ int ws[8];
    int t = threadIdx.x;
    int xv = (t < nb) ? btot[t] : 0;
    int lane = t & 31, w = t >> 5;
    int inc = xv;
#pragma unroll
    for (int o = 1; o < 32; o <<= 1) {
        int y = __shfl_up_sync(0xFFFFFFFFu, inc, o);
        if (lane >= o) inc += y;
    }
    if (lane == 31) ws[w] = inc;
    __syncthreads();
    int wbase = 0;
#pragma unroll
    for (int i = 0; i < 8; i++) wbase += (i < w) ? ws[i] : 0;
    if (t < nb) btot[t] = wbase + inc - xv;
}
__global__ void scan3_k(int* __restrict__ off, int* __restrict__ cur,
                        const int* __restrict__ btot, int n, int total)
{
    int i = blockIdx.x * blockDim.x + threadIdx.x;
    if (i < n) {
        int o = off[i] + btot[i >> 11];
        off[i] = o; cur[i] = o;
    }
    if (i == 0) off[n] = total;
}
__global__ void fill_k(const int* __restrict__ src, const int* __restrict__ dst,
                       const int* __restrict__ et, int* __restrict__ cur,
                       int* __restrict__ buf, int E, int NR)
{
    int e = blockIdx.x * blockDim.x + threadIdx.x;
    if (e >= E) return;
    int s = src[e], d = dst[e];
    int p1 = atomicAdd(&cur[s * R + et[e]], 1);
    buf[p1] = d;
    int p2 = atomicAdd(&cur[NR + d], 1);
    buf[p2] = s;
}

// ---------------- bf16x3 tensor-core GEMM -------------------------------------
// MODE: 1 bias+relu->fp32 | 2 bias+relu->bf16 | 3 bias->fp32+bf16 |
//       4 temporal gate->bf16 | 5 dual (y0 bias->C; y1 z + el/er) |
//       7 rel x2: two relations per CTA, CSR scatter via paired red.v4
#define AS_BUF 8192
#define BS_BUF 8704
#define OFF_AHI 0
#define OFF_ALO (2 * AS_BUF)
#define OFF_B5  (4 * AS_BUF)
#define SMEM_STD (4 * AS_BUF + 4 * BS_BUF)   // 67584
#define SMEM_REL (4 * AS_BUF + 8 * BS_BUF)   // 102400

template <int MODE>
__global__ __launch_bounds__(512)
void bf_gemm(const __nv_bfloat16* __restrict__ Ahi, const __nv_bfloat16* __restrict__ Alo,
             int lda,
             const uint32_t* __restrict__ Bhi, const uint32_t* __restrict__ Blo, long bstr,
             float* __restrict__ C, int ldc,
             __nv_bfloat16* __restrict__ obhi, __nv_bfloat16* __restrict__ oblo,
             int M, int K,
             const float* __restrict__ bias,
             float* __restrict__ zout, float* __restrict__ el, float* __restrict__ er,
             const float* __restrict__ attnl, const float* __restrict__ attnr,
             const int* __restrict__ csr_off, const int* __restrict__ csr_buf,
             float* __restrict__ hcat,
             const float* __restrict__ hcsrc, const float* __restrict__ gate_wlast,
             const float* __restrict__ tw_sum, float invE)
{
    extern __shared__ char sm[];
    const uint32_t smB = (uint32_t)__cvta_generic_to_shared(sm);
    constexpr int NREL = (MODE == 7) ? 2 : 1;

    const uint32_t* BhY = Bhi + (long)blockIdx.y * (NREL * bstr);
    const uint32_t* BlY = Blo + (long)blockIdx.y * (NREL * bstr);

    const int m0   = blockIdx.x * 128;
    const int tid  = threadIdx.x;
    const int lane = tid & 31;
    const int wid  = tid >> 5;
    const int grp  = lane >> 2;
    const int tig  = lane & 3;
    const int wm   = (wid >> 2) * 32;
    const int wn   = (wid & 3) * 32;

    const int aRow = tid >> 2;
    const int aC   = tid & 3;
    const int aSC  = aC ^ ((aRow >> 1) & 3);
    const int gmA  = m0 + aRow;
    const bool aOk = gmA < M;
    const long aSrcOff = (long)(aOk ? gmA : 0) * lda + aC * 8;
    const uint32_t aDst = aRow * 64 + aSC * 16;
    const int bRow = tid >> 5;
    const int bC   = tid & 31;
    const uint32_t bDst = bRow * 544 + bC * 16;
    const int bSrcOff = bRow * 128 + bC * 4;

    auto offB = [&](int b, int rel, int hl) -> uint32_t {
        return OFF_B5 + (uint32_t)(((b * NREL + rel) * 2 + hl) * BS_BUF);
    };
    auto issue = [&](int k0, int b) {
        cp16(smB + OFF_AHI + b * AS_BUF + aDst, Ahi + aSrcOff + k0, aOk);
        cp16(smB + OFF_ALO + b * AS_BUF + aDst, Alo + aSrcOff + k0, aOk);
#pragma unroll
        for (int rel = 0; rel < NREL; rel++) {
            cp16(smB + offB(b, rel, 0) + bDst, BhY + rel * bstr + (k0 >> 1) * 128 + bSrcOff, true);
            cp16(smB + offB(b, rel, 1) + bDst, BlY + rel * bstr + (k0 >> 1) * 128 + bSrcOff, true);
        }
        cp_commit();
    };

    float acc[NREL][2][4][4];
#pragma unroll
    for (int r = 0; r < NREL; r++)
#pragma unroll
        for (int i = 0; i < 2; i++)
#pragma unroll
            for (int j = 0; j < 4; j++)
#pragma unroll
                for (int k = 0; k < 4; k++) acc[r][i][j][k] = 0.f;

    const int arow_l  = wm + (lane & 15);
    const int aShift  = (arow_l >> 1) & 3;
    const int aChunk0 = lane >> 4;
    const uint32_t aRowByte = arow_l * 64;

    const int nch = K >> 5;
    issue(0, 0);

    for (int c = 0; c < nch; c++) {
        const int b = c & 1;
        if (c + 1 < nch) issue((c + 1) << 5, b ^ 1);
        if (c + 1 < nch) cp_wait<1>(); else cp_wait<0>();
        __syncthreads();

#pragma unroll
        for (int kc = 0; kc < 2; kc++) {
            uint32_t ah[2][4], al[2][4];
#pragma unroll
            for (int mt = 0; mt < 2; mt++) {
                const int sc = ((kc * 2 + aChunk0) ^ aShift) * 16;
                uint32_t off = aRowByte + mt * 1024 + sc;
                ldsm4(ah[mt], smB + OFF_AHI + b * AS_BUF + off);
                ldsm4(al[mt], smB + OFF_ALO + b * AS_BUF + off);
            }
            const int r0 = kc * 8 + tig;
            const uint32_t bo0 = (uint32_t)((r0 * 136 + wn + grp * 4) << 2);
            const uint32_t bo1 = (uint32_t)(((r0 + 4) * 136 + wn + grp * 4) << 2);
#pragma unroll
            for (int rel = 0; rel < NREL; rel++) {
                const char* bsH = sm + offB(b, rel, 0);
                const char* bsL = sm + offB(b, rel, 1);
                uint4 h0 = *(const uint4*)(bsH + bo0);
                uint4 h1 = *(const uint4*)(bsH + bo1);
                uint4 l0 = *(const uint4*)(bsL + bo0);
                uint4 l1 = *(const uint4*)(bsL + bo1);
                uint32_t bh[4][2], bl[4][2];
                bh[0][0] = h0.x; bh[1][0] = h0.y; bh[2][0] = h0.z; bh[3][0] = h0.w;
                bh[0][1] = h1.x; bh[1][1] = h1.y; bh[2][1] = h1.z; bh[3][1] = h1.w;
                bl[0][0] = l0.x; bl[1][0] = l0.y; bl[2][0] = l0.z; bl[3][0] = l0.w;
                bl[0][1] = l1.x; bl[1][1] = l1.y; bl[2][1] = l1.z; bl[3][1] = l1.w;
#pragma unroll
                for (int mt = 0; mt < 2; mt++)
#pragma unroll
                    for (int nt = 0; nt < 4; nt++) {
                        mma16816(acc[rel][mt][nt], ah[mt], bh[nt]);
                        mma16816(acc[rel][mt][nt], al[mt], bh[nt]);
                        mma16816(acc[rel][mt][nt], ah[mt], bl[nt]);
                    }
            }
        }
        __syncthreads();
    }

    // ================= epilogues =================
    if (MODE == 7) {
        const int g4   = (tig >> 1) * 4;
        const int ntb  = (tig & 1) * 2;
#pragma unroll
        for (int rel = 0; rel < NREL; rel++) {
            const int rY = blockIdx.y * NREL + rel;
#pragma unroll
            for (int mt = 0; mt < 2; mt++)
#pragma unroll
                for (int half = 0; half < 2; half++) {
                    const int gm = m0 + wm + mt * 16 + grp + half * 8;
                    float q[4][4];
#pragma unroll
                    for (int nt = 0; nt < 4; nt++) {
                        float v0 = acc[rel][mt][nt][half * 2 + 0];
                        float v1 = acc[rel][mt][nt][half * 2 + 1];
                        float o0 = __shfl_xor_sync(0xFFFFFFFFu, v0, 1);
                        float o1 = __shfl_xor_sync(0xFFFFFFFFu, v1, 1);
                        if ((tig & 1) == 0) { q[nt][0] = v0; q[nt][1] = v1; q[nt][2] = o0; q[nt][3] = o1; }
                        else                { q[nt][0] = o0; q[nt][1] = o1; q[nt][2] = v0; q[nt][3] = v1; }
                    }
                    if (gm >= M) continue;
                    const int key = gm * R + rY;
                    const int e0 = csr_off[key], e1 = csr_off[key + 1];
                    for (int e = e0; e < e1; e++) {
                        const int d = csr_buf[e];
                        float* basep = hcat + (long)d * 256 + wn + g4;
                        red_add_v4(basep + ntb * 8,
                                   q[ntb][0], q[ntb][1], q[ntb][2], q[ntb][3]);
                        red_add_v4(basep + (ntb + 1) * 8,
                                   q[ntb + 1][0], q[ntb + 1][1], q[ntb + 1][2], q[ntb + 1][3]);
                    }
                }
        }
        return;
    }

    if (MODE == 5 && blockIdx.y == 1) {
        const int h = wid & 3;
#pragma unroll
        for (int mt = 0; mt < 2; mt++)
#pragma unroll
            for (int half = 0; half < 2; half++) {
                const int gm = m0 + wm + mt * 16 + grp + half * 8;
                const bool ok = gm < M;
                float elp = 0.f, erp = 0.f;
#pragma unroll
                for (int nt = 0; nt < 4; nt++) {
                    const int n = wn + nt * 8 + 2 * tig;
                    float v0 = acc[0][mt][nt][half * 2 + 0];
                    float v1 = acc[0][mt][nt][half * 2 + 1];
                    if (ok) {
                        float2 o; o.x = v0; o.y = v1;
                        *(float2*)(zout + (long)gm * 128 + n) = o;
                    }
                    const int dh = nt * 8 + 2 * tig;
                    elp += v0 * attnl[h * 32 + dh] + v1 * attnl[h * 32 + dh + 1];
                    erp += v0 * attnr[h * 32 + dh] + v1 * attnr[h * 32 + dh + 1];
                }
                elp += __shfl_xor_sync(0xFFFFFFFFu, elp, 1);
                elp += __shfl_xor_sync(0xFFFFFFFFu, elp, 2);
                erp += __shfl_xor_sync(0xFFFFFFFFu, erp, 1);
                erp += __shfl_xor_sync(0xFFFFFFFFu, erp, 2);
                if (ok && tig == 0) {
                    el[gm * NH + h] = elp;
                    er[gm * NH + h] = erp;
                }
            }
        return;
    }

    float twm = 0.0f;
    if (MODE == 4) twm = tw_sum[0] * invE;

#pragma unroll
    for (int mt = 0; mt < 2; mt++)
#pragma unroll
        for (int nt = 0; nt < 4; nt++) {
            const int n = wn + nt * 8 + 2 * tig;
#pragma unroll
            for (int half = 0; half < 2; half++) {
                const int gm = m0 + wm + mt * 16 + grp + half * 8;
                if (gm >= M) continue;
                float v0 = acc[0][mt][nt][half * 2 + 0];
                float v1 = acc[0][mt][nt][half * 2 + 1];
                if (bias) { v0 += bias[n]; v1 += bias[n + 1]; }
                if (MODE == 1 || MODE == 2) { v0 = fmaxf(v0, 0.f); v1 = fmaxf(v1, 0.f); }
                if (MODE == 4) {
                    float g0 = v0 + twm * gate_wlast[n];
                    float g1 = v1 + twm * gate_wlast[n + 1];
                    g0 = 1.0f / (1.0f + expf(-g0));
                    g1 = 1.0f / (1.0f + expf(-g1));
                    float2 hc = *(const float2*)(hcsrc + (long)gm * 128 + n);
                    v0 = fmaxf(hc.x * g0, 0.f);
                    v1 = fmaxf(hc.y * g1, 0.f);
                }
                if (MODE == 1 || MODE == 3 || MODE == 5) {
                    float2 o; o.x = v0; o.y = v1;
                    *(float2*)(C + (long)gm * ldc + n) = o;
                }
                if (MODE == 2 || MODE == 3 || MODE == 4) {
                    __nv_bfloat162 H, Lw;
                    H.x = __float2bfloat16_rn(v0);
                    H.y = __float2bfloat16_rn(v1);
                    Lw.x = __float2bfloat16_rn(v0 - __bfloat162float(H.x));
                    Lw.y = __float2bfloat16_rn(v1 - __bfloat162float(H.y));
                    *(__nv_bfloat162*)(obhi + (long)gm * 128 + n) = H;
                    *(__nv_bfloat162*)(oblo + (long)gm * 128 + n) = Lw;
                }
            }
        }
}

// ---------------- GAT gather + fused bf16 conversion (replaces gather + cvt256) --
__global__ void gat_cvt_k(const int* __restrict__ off, const int* __restrict__ buf,
                          const float* __restrict__ el, const float* __restrict__ er,
                          const float* __restrict__ z, const float* __restrict__ bgat,
                          const float* __restrict__ hcat,
                          __nv_bfloat16* __restrict__ obhi, __nv_bfloat16* __restrict__ oblo,
                          int n, int NR)
{
    int node = (blockIdx.x * blockDim.x + threadIdx.x) >> 5;
    if (node >= n) return;
    int lane = threadIdx.x & 31;
    int d0 = lane * 4;
    int head = lane >> 3;

    // 1) convert rel half hcat[node, 0:128] -> bf16 hi/lo cols [0,128)
    float4 base = *(const float4*)(hcat + (long)node * 256 + d0);
    cvt4_store(base, obhi + (long)node * 256 + d0, oblo + (long)node * 256 + d0);

    // 2) GAT gather (atomic-free, unroll x2) -> bf16 hi/lo cols [128,256)
    int e0 = off[NR + node], e1 = off[NR + node + 1];
    float erv = er[node * NH + head];
    float ax0 = 0.f, ay0 = 0.f, az0 = 0.f, aw0 = 0.f, sx0 = 0.f;
    float ax1 = 0.f, ay1 = 0.f, az1 = 0.f, aw1 = 0.f, sx1 = 0.f;
    int j = e0;
    for (; j + 1 < e1; j += 2) {
        int s0 = buf[j], s1 = buf[j + 1];
        float v0 = el[s0 * NH + head] + erv;
        float v1 = el[s1 * NH + head] + erv;
        v0 = (v0 >= 0.f) ? v0 : 0.2f * v0;
        v1 = (v1 >= 0.f) ? v1 : 0.2f * v1;
        float ex0 = __expf(v0), ex1 = __expf(v1);
        float4 z0 = *(const float4*)(z + (long)s0 * 128 + d0);
        float4 z1 = *(const float4*)(z + (long)s1 * 128 + d0);
        sx0 += ex0; sx1 += ex1;
        ax0 = fmaf(ex0, z0.x, ax0); ay0 = fmaf(ex0, z0.y, ay0);
        az0 = fmaf(ex0, z0.z, az0); aw0 = fmaf(ex0, z0.w, aw0);
        ax1 = fmaf(ex1, z1.x, ax1); ay1 = fmaf(ex1, z1.y, ay1);
        az1 = fmaf(ex1, z1.z, az1); aw1 = fmaf(ex1, z1.w, aw1);
    }
    if (j < e1) {
        int s0 = buf[j];
        float v0 = el[s0 * NH + head] + erv;
        v0 = (v0 >= 0.f) ? v0 : 0.2f * v0;
        float ex0 = __expf(v0);
        float4 z0 = *(const float4*)(z + (long)s0 * 128 + d0);
        sx0 += ex0;
        ax0 = fmaf(ex0, z0.x, ax0); ay0 = fmaf(ex0, z0.y, ay0);
        az0 = fmaf(ex0, z0.z, az0); aw0 = fmaf(ex0, z0.w, aw0);
    }
    float sx = sx0 + sx1;
    float inv = (e1 > e0) ? (1.0f / sx) : 0.0f;
    float4 bg = *(const float4*)(bgat + d0);
    float4 o;
    o.x = fmaf(ax0 + ax1, inv, bg.x); o.y = fmaf(ay0 + ay1, inv, bg.y);
    o.z = fmaf(az0 + az1, inv, bg.z); o.w = fmaf(aw0 + aw1, inv, bg.w);
    cvt4_store(o, obhi + (long)node * 256 + 128 + d0, oblo + (long)node * 256 + 128 + d0);
}

// ---------------- misc ------------------------------------------------------------
__global__ void zero_scalar_k(float* p) { *p = 0.0f; }
__global__ void reduce_sum_k(const float* __restrict__ x, float* out, int n) {
    float s = 0.0f;
    for (int i = blockIdx.x * blockDim.x + threadIdx.x; i < n; i += gridDim.x * blockDim.x)
        s += x[i];
#pragma unroll
    for (int o = 16; o > 0; o >>= 1) s += __shfl_xor_sync(0xFFFFFFFFu, s, o);
    __shared__ float ws[8];
    if ((threadIdx.x & 31) == 0) ws[threadIdx.x >> 5] = s;
    __syncthreads();
    if (threadIdx.x < 32) {
        s = (threadIdx.x < (blockDim.x >> 5)) ? ws[threadIdx.x] : 0.0f;
#pragma unroll
        for (int o = 4; o > 0; o >>= 1) s += __shfl_xor_sync(0xFFFFFFFFu, s, o);
        if (threadIdx.x == 0) atomicAdd(out, s);
    }
}

// ---------------- launcher ----------------------------------------------------------
extern "C" void kernel_launch(void* const* d_in, const int* in_sizes, int n_in,
                              void* d_out, int out_size)
{
    const float* feat   = (const float*)d_in[0];
    const int*   src    = (const int*)  d_in[1];
    const int*   dst    = (const int*)  d_in[2];
    const int*   et     = (const int*)  d_in[3];
    const float* tw     = (const float*)d_in[4];
    const float* W_rel  = (const float*)d_in[5];
    const float* b_rel  = (const float*)d_in[6];
    const float* W_loop = (const float*)d_in[7];
    const float* W_gat  = (const float*)d_in[8];
    const float* attn_l = (const float*)d_in[9];
    const float* attn_r = (const float*)d_in[10];
    const float* b_gat  = (const float*)d_in[11];
    const float* W_fuse = (const float*)d_in[12];
    const float* b_fuse = (const float*)d_in[13];
    const float* W_gate = (const float*)d_in[14];
    const float* b_gate = (const float*)d_in[15];

    const int Nn = in_sizes[0] / D;
    const int E  = in_sizes[1];
    const int NR = Nn * R;
    const int NK = NR + Nn;

    cudaFuncSetAttribute(bf_gemm<1>, cudaFuncAttributeMaxDynamicSharedMemorySize, SMEM_STD);
    cudaFuncSetAttribute(bf_gemm<2>, cudaFuncAttributeMaxDynamicSharedMemorySize, SMEM_STD);
    cudaFuncSetAttribute(bf_gemm<3>, cudaFuncAttributeMaxDynamicSharedMemorySize, SMEM_STD);
    cudaFuncSetAttribute(bf_gemm<4>, cudaFuncAttributeMaxDynamicSharedMemorySize, SMEM_STD);
    cudaFuncSetAttribute(bf_gemm<5>, cudaFuncAttributeMaxDynamicSharedMemorySize, SMEM_STD);
    cudaFuncSetAttribute(bf_gemm<7>, cudaFuncAttributeMaxDynamicSharedMemorySize, SMEM_REL);

    float *hcat, *z, *el, *er, *tws;
    int *cnt, *off, *cur, *btot, *buf;
    __nv_bfloat16 *Ahi, *Alo, *Bhi_a, *Blo_a;
    uint32_t *whi, *wlo;
    cudaGetSymbolAddress((void**)&hcat, g_hcat);
    cudaGetSymbolAddress((void**)&z,    g_z);
    cudaGetSymbolAddress((void**)&el,   g_el);
    cudaGetSymbolAddress((void**)&er,   g_er);
    cudaGetSymbolAddress((void**)&tws,  g_twsum);
    cudaGetSymbolAddress((void**)&cnt,  g_cnt);
    cudaGetSymbolAddress((void**)&off,  g_off);
    cudaGetSymbolAddress((void**)&cur,  g_cur);
    cudaGetSymbolAddress((void**)&btot, g_btot);
    cudaGetSymbolAddress((void**)&buf,  g_buf);
    cudaGetSymbolAddress((void**)&Ahi,  g_ahi);
    cudaGetSymbolAddress((void**)&Alo,  g_alo);
    cudaGetSymbolAddress((void**)&Bhi_a, g_bhi);
    cudaGetSymbolAddress((void**)&Blo_a, g_blo);
    cudaGetSymbolAddress((void**)&whi,  g_wpk_hi);
    cudaGetSymbolAddress((void**)&wlo,  g_wpk_lo);

    const int MB = (Nn + 127) / 128;
    const int TPB = 256;
    const int e_blocks      = (E + TPB - 1) / TPB;
    const int nk_blocks     = (NK + TPB - 1) / TPB;
    const int nb            = (NK + 2047) / 2048;
    const int gat_blocks    = (Nn + 7) / 8;
    const int cvt128_blocks = (Nn * D / 4 + TPB - 1) / TPB;

    zero_scalar_k<<<1, 1>>>(tws);
    reduce_sum_k<<<256, 256>>>(tw, tws, E);

    zero_int_k<<<nk_blocks, TPB>>>(cnt, NK);
    hist_k<<<e_blocks, TPB>>>(src, dst, et, cnt, E, NR);
    scan1_k<<<nb, 256>>>(cnt, off, btot, NK);
    scan2_k<<<1, 256>>>(btot, nb);
    scan3_k<<<nk_blocks, TPB>>>(off, cur, btot, NK, 2 * E);
    fill_k<<<e_blocks, TPB>>>(src, dst, et, cur, buf, E, NR);

    cvt_wt_k<<<(3072 * 128 + TPB - 1) / TPB, TPB>>>(W_rel,  whi,              wlo,              3072);
    cvt_wt_k<<<(192 * 128 + TPB - 1) / TPB, TPB>>>(W_loop, whi + 3072 * 128, wlo + 3072 * 128, 192);
    cvt_wt_k<<<(192 * 128 + TPB - 1) / TPB, TPB>>>(W_gat,  whi + 3264 * 128, wlo + 3264 * 128, 192);
    cvt_wt_k<<<(128 * 128 + TPB - 1) / TPB, TPB>>>(W_fuse, whi + 3456 * 128, wlo + 3456 * 128, 128);
    cvt_wt_k<<<(64 * 128 + TPB - 1) / TPB, TPB>>>(W_gate, whi + 3584 * 128, wlo + 3584 * 128, 64);

    cvt_act_k<<<cvt128_blocks, TPB>>>(feat, Ahi, Alo, Nn * D / 4);

    __nv_bfloat16 *cur_hi = Ahi, *cur_lo = Alo;
    __nv_bfloat16 *oth_hi = Bhi_a, *oth_lo = Blo_a;

    for (int l = 0; l < NL; l++) {
        const float* brel_l = b_rel  + l * D;
        const float* bgat_l = b_gat  + l * D;
        const float* al_l   = attn_l + l * NH * DH;
        const float* ar_l   = attn_r + l * NH * DH;
        const uint32_t* wrel_hi  = whi + (long)(l * 1024) * 128;
        const uint32_t* wrel_lo  = wlo + (long)(l * 1024) * 128;
        const uint32_t* wloop_hi = whi + (long)(3072 + l * 64) * 128;
        const uint32_t* wloop_lo = wlo + (long)(3072 + l * 64) * 128;

        // 1) dual GEMM: y0 -> hcat[:,0:128] = X@W_loop + b_rel ; y1 -> z + el/er
        bf_gemm<5><<<dim3(MB, 2), 512, SMEM_STD>>>(
            cur_hi, cur_lo, D, wloop_hi, wloop_lo, (long)192 * 128,
            hcat, 2 * D, nullptr, nullptr,
            Nn, D, brel_l,
            z, el, er, al_l, ar_l,
            nullptr, nullptr, nullptr, nullptr, nullptr, nullptr, 0.f);

        // 2) rel GEMM, 2 relations per CTA, fused CSR scatter
        bf_gemm<7><<<dim3(MB, R / 2), 512, SMEM_REL>>>(
            cur_hi, cur_lo, D, wrel_hi, wrel_lo, 64 * 128,
            nullptr, 0, nullptr, nullptr,
            Nn, D, nullptr,
            nullptr, nullptr, nullptr, nullptr, nullptr,
            off, buf, hcat,
            nullptr, nullptr, nullptr, 0.f);

        // 3) GAT gather + fused bf16 conversion of both halves -> oth buffers
        gat_cvt_k<<<gat_blocks, TPB>>>(off, buf, el, er, z, bgat_l, hcat,
                                       oth_hi, oth_lo, Nn, NR);

        // 4) fuse (+ gate at layer 0)
        if (l == 0) {
            bf_gemm<3><<<dim3(MB, 1), 512, SMEM_STD>>>(
                oth_hi, oth_lo, 2 * D, whi + (long)3456 * 128, wlo + (long)3456 * 128, 0,
                z, D, cur_hi, cur_lo,
                Nn, 2 * D, b_fuse,
                nullptr, nullptr, nullptr, nullptr, nullptr,
                nullptr, nullptr, nullptr, nullptr, nullptr, nullptr, 0.f);
            bf_gemm<4><<<dim3(MB, 1), 512, SMEM_STD>>>(
                cur_hi, cur_lo, D, whi + (long)3584 * 128, wlo + (long)3584 * 128, 0,
                nullptr, 0, oth_hi, oth_lo,
                Nn, D, b_gate,
                nullptr, nullptr, nullptr, nullptr, nullptr,
                nullptr, nullptr, nullptr,
                z, W_gate + (long)D * D, tws, 1.0f / (float)E);
            __nv_bfloat16* t;
            t = cur_hi; cur_hi = oth_hi; oth_hi = t;
            t = cur_lo; cur_lo = oth_lo; oth_lo = t;
        } else if (l < NL - 1) {
            bf_gemm<2><<<dim3(MB, 1), 512, SMEM_STD>>>(
                oth_hi, oth_lo, 2 * D, whi + (long)3456 * 128, wlo + (long)3456 * 128, 0,
                nullptr, 0, cur_hi, cur_lo,
                Nn, 2 * D, b_fuse,
                nullptr, nullptr, nullptr, nullptr, nullptr,
                nullptr, nullptr, nullptr, nullptr, nullptr, nullptr, 0.f);
        } else {
            bf_gemm<1><<<dim3(MB, 1), 512, SMEM_STD>>>(
                oth_hi, oth_lo, 2 * D, whi + (long)3456 * 128, wlo + (long)3456 * 128, 0,
                (float*)d_out, D, nullptr, nullptr,
                Nn, 2 * D, b_fuse,
                nullptr, nullptr, nullptr, nullptr, nullptr,
                nullptr, nullptr, nullptr, nullptr, nullptr, nullptr, 0.f);
        }
    }
}

// round 13
// speedup vs baseline: 1.0938x; 1.0021x over previous
#include <cuda_runtime.h>
#include <cuda_bf16.h>
#include <math.h>
#include <stdint.h>

// Problem constants: N=30000, E=480000, D=128, R=16, H=4, DH=32, L=3
#define MAXN 30000
#define MAXE 480000
#define D 128
#define R 16
#define NH 4
#define DH 32
#define NL 3
#define NKMAX (MAXN * (R + 1))

// ---------------- scratch ----------------------------------------------------
__device__ float g_hcat[(long)MAXN * (2 * D)];
__device__ float g_z[(long)MAXN * D];
__device__ float g_el[MAXN * NH];
__device__ float g_er[MAXN * NH];
__device__ float g_twsum;
__device__ int g_cnt[NKMAX];
__device__ int g_off[NKMAX + 1];
__device__ int g_cur[NKMAX];
__device__ int g_btot[512];
__device__ int g_buf[2 * MAXE];
// two bf16 hi/lo activation buffer pairs (max K = 256)
__device__ __nv_bfloat16 g_ahi[(long)MAXN * 256];
__device__ __nv_bfloat16 g_alo[(long)MAXN * 256];
__device__ __nv_bfloat16 g_bhi[(long)MAXN * 256];
__device__ __nv_bfloat16 g_blo[(long)MAXN * 256];
// packed bf16-pair weights (rows of 128 words, column-permuted):
//   [0,3072): W_rel (3 x 16 x 64)  [3072,3264): W_loop (3x64) [3264,3456): W_gat (3x64)
//   [3456,3584): W_fuse            [3584,3648): W_gate
#define WPK_ROWS 3648
__device__ uint32_t g_wpk_hi[WPK_ROWS * 128];
__device__ uint32_t g_wpk_lo[WPK_ROWS * 128];

// ---------------- helpers ----------------------------------------------------
__device__ __forceinline__ void red_add_v4(float* p, float x, float y, float z, float w) {
    asm volatile("red.global.add.v4.f32 [%0], {%1, %2, %3, %4};"
                 :: "l"(p), "f"(x), "f"(y), "f"(z), "f"(w) : "memory");
}
__device__ __forceinline__ void ldsm4(uint32_t r[4], uint32_t addr) {
    asm volatile("ldmatrix.sync.aligned.m8n8.x4.shared.b16 {%0,%1,%2,%3}, [%4];"
                 : "=r"(r[0]), "=r"(r[1]), "=r"(r[2]), "=r"(r[3]) : "r"(addr));
}
__device__ __forceinline__ void mma16816(float c[4], const uint32_t a[4], const uint32_t b[2]) {
    asm volatile("mma.sync.aligned.m16n8k16.row.col.f32.bf16.bf16.f32 "
                 "{%0,%1,%2,%3}, {%4,%5,%6,%7}, {%8,%9}, {%0,%1,%2,%3};"
                 : "+f"(c[0]), "+f"(c[1]), "+f"(c[2]), "+f"(c[3])
                 : "r"(a[0]), "r"(a[1]), "r"(a[2]), "r"(a[3]), "r"(b[0]), "r"(b[1]));
}
__device__ __forceinline__ void cp16(uint32_t dst, const void* src, bool pred) {
    int sz = pred ? 16 : 0;
    asm volatile("cp.async.cg.shared.global [%0], [%1], 16, %2;"
                 :: "r"(dst), "l"(src), "r"(sz));
}
__device__ __forceinline__ void cp_commit() { asm volatile("cp.async.commit_group;"); }
template <int NN> __device__ __forceinline__ void cp_wait() {
    asm volatile("cp.async.wait_group %0;" :: "n"(NN));
}
// convert 4 floats -> bf16 hi/lo pairs
__device__ __forceinline__ void cvt4_store(float4 v, __nv_bfloat16* hi, __nv_bfloat16* lo) {
    __nv_bfloat162 H0, H1, L0, L1;
    H0.x = __float2bfloat16_rn(v.x); H0.y = __float2bfloat16_rn(v.y);
    H1.x = __float2bfloat16_rn(v.z); H1.y = __float2bfloat16_rn(v.w);
    L0.x = __float2bfloat16_rn(v.x - __bfloat162float(H0.x));
    L0.y = __float2bfloat16_rn(v.y - __bfloat162float(H0.y));
    L1.x = __float2bfloat16_rn(v.z - __bfloat162float(H1.x));
    L1.y = __float2bfloat16_rn(v.w - __bfloat162float(H1.y));
    ((__nv_bfloat162*)hi)[0] = H0; ((__nv_bfloat162*)hi)[1] = H1;
    ((__nv_bfloat162*)lo)[0] = L0; ((__nv_bfloat162*)lo)[1] = L1;
}

// ---------------- conversion kernels ------------------------------------------
__global__ void cvt_act_k(const float* __restrict__ x,
                          __nv_bfloat16* __restrict__ hi, __nv_bfloat16* __restrict__ lo,
                          int total4)
{
    int i = blockIdx.x * blockDim.x + threadIdx.x;
    if (i >= total4) return;
    float4 v = ((const float4*)x)[i];
    cvt4_store(v, hi + i * 4, lo + i * 4);
}

// unified weight conversion: all 3648 packed rows in one launch
__global__ void cvt_wt_all_k(const float* __restrict__ W_rel, const float* __restrict__ W_loop,
                             const float* __restrict__ W_gat, const float* __restrict__ W_fuse,
                             const float* __restrict__ W_gate,
                             uint32_t* __restrict__ hi, uint32_t* __restrict__ lo)
{
    int i = blockIdx.x * blockDim.x + threadIdx.x;
    if (i >= WPK_ROWS * 128) return;
    int r = i >> 7, n = i & 127;
    const float* src; int k2;
    if (r < 3072)      { src = W_rel;  k2 = r; }
    else if (r < 3264) { src = W_loop; k2 = r - 3072; }
    else if (r < 3456) { src = W_gat;  k2 = r - 3264; }
    else if (r < 3584) { src = W_fuse; k2 = r - 3456; }
    else               { src = W_gate; k2 = r - 3584; }
    float a = src[(long)(2 * k2) * 128 + n];
    float b = src[(long)(2 * k2 + 1) * 128 + n];
    __nv_bfloat16 ah = __float2bfloat16_rn(a), bh = __float2bfloat16_rn(b);
    __nv_bfloat162 H; H.x = ah; H.y = bh;
    __nv_bfloat162 Lw;
    Lw.x = __float2bfloat16_rn(a - __bfloat162float(ah));
    Lw.y = __float2bfloat16_rn(b - __bfloat162float(bh));
    int np = (n & ~31) | ((n & 7) << 2) | ((n >> 3) & 3);
    hi[(long)r * 128 + np] = *(uint32_t*)&H;
    lo[(long)r * 128 + np] = *(uint32_t*)&Lw;
}

// ---------------- CSR build ----------------------------------------------------
__global__ void zero_int_k(int* p, int n, float* tws) {
    int i = blockIdx.x * blockDim.x + threadIdx.x;
    if (i < n) p[i] = 0;
    if (i == 0 && tws) *tws = 0.0f;
}
__global__ void hist_k(const int* __restrict__ src, const int* __restrict__ dst,
                       const int* __restrict__ et, int* __restrict__ cnt, int E, int NR)
{
    int e = blockIdx.x * blockDim.x + threadIdx.x;
    if (e >= E) return;
    atomicAdd(&cnt[src[e] * R + et[e]], 1);
    atomicAdd(&cnt[NR + dst[e]], 1);
}
__global__ void scan1_k(const int* __restrict__ cnt, int* __restrict__ off,
                        int* __restrict__ btot, int n)
{
    __shared__ int ws[8];
    int t = threadIdx.x;
    int base = blockIdx.x * 2048 + t * 8;
    int v[8], s = 0;
#pragma unroll
    for (int i = 0; i < 8; i++) {
        int x = (base + i < n) ? cnt[base + i] : 0;
        v[i] = s; s += x;
    }
    int lane = t & 31, w = t >> 5;
    int inc = s;
#pragma unroll
    for (int o = 1; o < 32; o <<= 1) {
        int y = __shfl_up_sync(0xFFFFFFFFu, inc, o);
        if (lane >= o) inc += y;
    }
    if (lane == 31) ws[w] = inc;
    int texc = inc - s;
    __syncthreads();
    int wbase = 0;
#pragma unroll
    for (int i = 0; i < 8; i++) wbase += (i < w) ? ws[i] : 0;
#pragma unroll
    for (int i = 0; i < 8; i++)
        if (base + i < n) off[base + i] = wbase + texc + v[i];
    if (t == 255) btot[blockIdx.x] = wbase + inc;
}
__global__ void scan2_k(int* btot, int nb) {
    __shared__ int ws[8];
    int t = threadIdx.x;
    int xv = (t < nb) ? btot[t] : 0;
    int lane = t & 31, w = t >> 5;
    int inc = xv;
#pragma unroll
    for (int o = 1; o < 32; o <<= 1) {
        int y = __shfl_up_sync(0xFFFFFFFFu, inc, o);
        if (lane >= o) inc += y;
    }
    if (lane == 31) ws[w] = inc;
    __syncthreads();
    int wbase = 0;
#pragma unroll
    for (int i = 0; i < 8; i++) wbase += (i < w) ? ws[i] : 0;
    if (t < nb) btot[t] = wbase + inc - xv;
}
__global__ void scan3_k(int* __restrict__ off, int* __restrict__ cur,
                        const int* __restrict__ btot, int n, int total)
{
    int i = blockIdx.x * blockDim.x + threadIdx.x;
    if (i < n) {
        int o = off[i] + btot[i >> 11];
        off[i] = o; cur[i] = o;
    }
    if (i == 0) off[n] = total;
}
__global__ void fill_k(const int* __restrict__ src, const int* __restrict__ dst,
                       const int* __restrict__ et, int* __restrict__ cur,
                       int* __restrict__ buf, int E, int NR)
{
    int e = blockIdx.x * blockDim.x + threadIdx.x;
    if (e >= E) return;
    int s = src[e], d = dst[e];
    int p1 = atomicAdd(&cur[s * R + et[e]], 1);
    buf[p1] = d;
    int p2 = atomicAdd(&cur[NR + d], 1);
    buf[p2] = s;
}

// ---------------- bf16x3 tensor-core GEMM -------------------------------------
// MODE: 1 bias+relu->fp32 | 2 bias+relu->bf16 | 3 bias->fp32+bf16 |
//       4 temporal gate->bf16 | 5 dual (y0 bias->C; y1 z + el/er) |
//       7 rel x2: two relations per CTA, CSR scatter via paired red.v4
#define AS_BUF 8192
#define BS_BUF 8704
#define OFF_AHI 0
#define OFF_ALO (2 * AS_BUF)
#define OFF_B5  (4 * AS_BUF)
#define SMEM_STD (4 * AS_BUF + 4 * BS_BUF)   // 67584
#define SMEM_REL (4 * AS_BUF + 8 * BS_BUF)   // 102400

template <int MODE>
__global__ __launch_bounds__(512)
void bf_gemm(const __nv_bfloat16* __restrict__ Ahi, const __nv_bfloat16* __restrict__ Alo,
             int lda,
             const uint32_t* __restrict__ Bhi, const uint32_t* __restrict__ Blo, long bstr,
             float* __restrict__ C, int ldc,
             __nv_bfloat16* __restrict__ obhi, __nv_bfloat16* __restrict__ oblo,
             int M, int K,
             const float* __restrict__ bias,
             float* __restrict__ zout, float* __restrict__ el, float* __restrict__ er,
             const float* __restrict__ attnl, const float* __restrict__ attnr,
             const int* __restrict__ csr_off, const int* __restrict__ csr_buf,
             float* __restrict__ hcat,
             const float* __restrict__ hcsrc, const float* __restrict__ gate_wlast,
             const float* __restrict__ tw_sum, float invE)
{
    extern __shared__ char sm[];
    const uint32_t smB = (uint32_t)__cvta_generic_to_shared(sm);
    constexpr int NREL = (MODE == 7) ? 2 : 1;

    const uint32_t* BhY = Bhi + (long)blockIdx.y * (NREL * bstr);
    const uint32_t* BlY = Blo + (long)blockIdx.y * (NREL * bstr);

    const int m0   = blockIdx.x * 128;
    const int tid  = threadIdx.x;
    const int lane = tid & 31;
    const int wid  = tid >> 5;
    const int grp  = lane >> 2;
    const int tig  = lane & 3;
    const int wm   = (wid >> 2) * 32;
    const int wn   = (wid & 3) * 32;

    const int aRow = tid >> 2;
    const int aC   = tid & 3;
    const int aSC  = aC ^ ((aRow >> 1) & 3);
    const int gmA  = m0 + aRow;
    const bool aOk = gmA < M;
    const long aSrcOff = (long)(aOk ? gmA : 0) * lda + aC * 8;
    const uint32_t aDst = aRow * 64 + aSC * 16;
    const int bRow = tid >> 5;
    const int bC   = tid & 31;
    const uint32_t bDst = bRow * 544 + bC * 16;
    const int bSrcOff = bRow * 128 + bC * 4;

    auto offB = [&](int b, int rel, int hl) -> uint32_t {
        return OFF_B5 + (uint32_t)(((b * NREL + rel) * 2 + hl) * BS_BUF);
    };
    auto issue = [&](int k0, int b) {
        cp16(smB + OFF_AHI + b * AS_BUF + aDst, Ahi + aSrcOff + k0, aOk);
        cp16(smB + OFF_ALO + b * AS_BUF + aDst, Alo + aSrcOff + k0, aOk);
#pragma unroll
        for (int rel = 0; rel < NREL; rel++) {
            cp16(smB + offB(b, rel, 0) + bDst, BhY + rel * bstr + (k0 >> 1) * 128 + bSrcOff, true);
            cp16(smB + offB(b, rel, 1) + bDst, BlY + rel * bstr + (k0 >> 1) * 128 + bSrcOff, true);
        }
        cp_commit();
    };

    float acc[NREL][2][4][4];
#pragma unroll
    for (int r = 0; r < NREL; r++)
#pragma unroll
        for (int i = 0; i < 2; i++)
#pragma unroll
            for (int j = 0; j < 4; j++)
#pragma unroll
                for (int k = 0; k < 4; k++) acc[r][i][j][k] = 0.f;

    const int arow_l  = wm + (lane & 15);
    const int aShift  = (arow_l >> 1) & 3;
    const int aChunk0 = lane >> 4;
    const uint32_t aRowByte = arow_l * 64;

    const int nch = K >> 5;
    issue(0, 0);

    for (int c = 0; c < nch; c++) {
        const int b = c & 1;
        if (c + 1 < nch) issue((c + 1) << 5, b ^ 1);
        if (c + 1 < nch) cp_wait<1>(); else cp_wait<0>();
        __syncthreads();

#pragma unroll
        for (int kc = 0; kc < 2; kc++) {
            uint32_t ah[2][4], al[2][4];
#pragma unroll
            for (int mt = 0; mt < 2; mt++) {
                const int sc = ((kc * 2 + aChunk0) ^ aShift) * 16;
                uint32_t off = aRowByte + mt * 1024 + sc;
                ldsm4(ah[mt], smB + OFF_AHI + b * AS_BUF + off);
                ldsm4(al[mt], smB + OFF_ALO + b * AS_BUF + off);
            }
            const int r0 = kc * 8 + tig;
            const uint32_t bo0 = (uint32_t)((r0 * 136 + wn + grp * 4) << 2);
            const uint32_t bo1 = (uint32_t)(((r0 + 4) * 136 + wn + grp * 4) << 2);
#pragma unroll
            for (int rel = 0; rel < NREL; rel++) {
                const char* bsH = sm + offB(b, rel, 0);
                const char* bsL = sm + offB(b, rel, 1);
                uint4 h0 = *(const uint4*)(bsH + bo0);
                uint4 h1 = *(const uint4*)(bsH + bo1);
                uint4 l0 = *(const uint4*)(bsL + bo0);
                uint4 l1 = *(const uint4*)(bsL + bo1);
                uint32_t bh[4][2], bl[4][2];
                bh[0][0] = h0.x; bh[1][0] = h0.y; bh[2][0] = h0.z; bh[3][0] = h0.w;
                bh[0][1] = h1.x; bh[1][1] = h1.y; bh[2][1] = h1.z; bh[3][1] = h1.w;
                bl[0][0] = l0.x; bl[1][0] = l0.y; bl[2][0] = l0.z; bl[3][0] = l0.w;
                bl[0][1] = l1.x; bl[1][1] = l1.y; bl[2][1] = l1.z; bl[3][1] = l1.w;
#pragma unroll
                for (int mt = 0; mt < 2; mt++)
#pragma unroll
                    for (int nt = 0; nt < 4; nt++) {
                        mma16816(acc[rel][mt][nt], ah[mt], bh[nt]);
                        mma16816(acc[rel][mt][nt], al[mt], bh[nt]);
                        mma16816(acc[rel][mt][nt], ah[mt], bl[nt]);
                    }
            }
        }
        __syncthreads();
    }

    // ================= epilogues =================
    if (MODE == 7) {
        const int g4   = (tig >> 1) * 4;
        const int ntb  = (tig & 1) * 2;
#pragma unroll
        for (int rel = 0; rel < NREL; rel++) {
            const int rY = blockIdx.y * NREL + rel;
#pragma unroll
            for (int mt = 0; mt < 2; mt++)
#pragma unroll
                for (int half = 0; half < 2; half++) {
                    const int gm = m0 + wm + mt * 16 + grp + half * 8;
                    float q[4][4];
#pragma unroll
                    for (int nt = 0; nt < 4; nt++) {
                        float v0 = acc[rel][mt][nt][half * 2 + 0];
                        float v1 = acc[rel][mt][nt][half * 2 + 1];
                        float o0 = __shfl_xor_sync(0xFFFFFFFFu, v0, 1);
                        float o1 = __shfl_xor_sync(0xFFFFFFFFu, v1, 1);
                        if ((tig & 1) == 0) { q[nt][0] = v0; q[nt][1] = v1; q[nt][2] = o0; q[nt][3] = o1; }
                        else                { q[nt][0] = o0; q[nt][1] = o1; q[nt][2] = v0; q[nt][3] = v1; }
                    }
                    if (gm >= M) continue;
                    const int key = gm * R + rY;
                    const int e0 = csr_off[key], e1 = csr_off[key + 1];
                    for (int e = e0; e < e1; e++) {
                        const int d = csr_buf[e];
                        float* basep = hcat + (long)d * 256 + wn + g4;
                        red_add_v4(basep + ntb * 8,
                                   q[ntb][0], q[ntb][1], q[ntb][2], q[ntb][3]);
                        red_add_v4(basep + (ntb + 1) * 8,
                                   q[ntb + 1][0], q[ntb + 1][1], q[ntb + 1][2], q[ntb + 1][3]);
                    }
                }
        }
        return;
    }

    if (MODE == 5 && blockIdx.y == 1) {
        const int h = wid & 3;
#pragma unroll
        for (int mt = 0; mt < 2; mt++)
#pragma unroll
            for (int half = 0; half < 2; half++) {
                const int gm = m0 + wm + mt * 16 + grp + half * 8;
                const bool ok = gm < M;
                float elp = 0.f, erp = 0.f;
#pragma unroll
                for (int nt = 0; nt < 4; nt++) {
                    const int n = wn + nt * 8 + 2 * tig;
                    float v0 = acc[0][mt][nt][half * 2 + 0];
                    float v1 = acc[0][mt][nt][half * 2 + 1];
                    if (ok) {
                        float2 o; o.x = v0; o.y = v1;
                        *(float2*)(zout + (long)gm * 128 + n) = o;
                    }
                    const int dh = nt * 8 + 2 * tig;
                    elp += v0 * attnl[h * 32 + dh] + v1 * attnl[h * 32 + dh + 1];
                    erp += v0 * attnr[h * 32 + dh] + v1 * attnr[h * 32 + dh + 1];
                }
                elp += __shfl_xor_sync(0xFFFFFFFFu, elp, 1);
                elp += __shfl_xor_sync(0xFFFFFFFFu, elp, 2);
                erp += __shfl_xor_sync(0xFFFFFFFFu, erp, 1);
                erp += __shfl_xor_sync(0xFFFFFFFFu, erp, 2);
                if (ok && tig == 0) {
                    el[gm * NH + h] = elp;
                    er[gm * NH + h] = erp;
                }
            }
        return;
    }

    float twm = 0.0f;
    if (MODE == 4) twm = tw_sum[0] * invE;

#pragma unroll
    for (int mt = 0; mt < 2; mt++)
#pragma unroll
        for (int nt = 0; nt < 4; nt++) {
            const int n = wn + nt * 8 + 2 * tig;
#pragma unroll
            for (int half = 0; half < 2; half++) {
                const int gm = m0 + wm + mt * 16 + grp + half * 8;
                if (gm >= M) continue;
                float v0 = acc[0][mt][nt][half * 2 + 0];
                float v1 = acc[0][mt][nt][half * 2 + 1];
                if (bias) { v0 += bias[n]; v1 += bias[n + 1]; }
                if (MODE == 1 || MODE == 2) { v0 = fmaxf(v0, 0.f); v1 = fmaxf(v1, 0.f); }
                if (MODE == 4) {
                    float g0 = v0 + twm * gate_wlast[n];
                    float g1 = v1 + twm * gate_wlast[n + 1];
                    g0 = 1.0f / (1.0f + expf(-g0));
                    g1 = 1.0f / (1.0f + expf(-g1));
                    float2 hc = *(const float2*)(hcsrc + (long)gm * 128 + n);
                    v0 = fmaxf(hc.x * g0, 0.f);
                    v1 = fmaxf(hc.y * g1, 0.f);
                }
                if (MODE == 1 || MODE == 3 || MODE == 5) {
                    float2 o; o.x = v0; o.y = v1;
                    *(float2*)(C + (long)gm * ldc + n) = o;
                }
                if (MODE == 2 || MODE == 3 || MODE == 4) {
                    __nv_bfloat162 H, Lw;
                    H.x = __float2bfloat16_rn(v0);
                    H.y = __float2bfloat16_rn(v1);
                    Lw.x = __float2bfloat16_rn(v0 - __bfloat162float(H.x));
                    Lw.y = __float2bfloat16_rn(v1 - __bfloat162float(H.y));
                    *(__nv_bfloat162*)(obhi + (long)gm * 128 + n) = H;
                    *(__nv_bfloat162*)(oblo + (long)gm * 128 + n) = Lw;
                }
            }
        }
}

// ---------------- GAT gather + fused bf16 conversion ------------------------------
__global__ void gat_cvt_k(const int* __restrict__ off, const int* __restrict__ buf,
                          const float* __restrict__ el, const float* __restrict__ er,
                          const float* __restrict__ z, const float* __restrict__ bgat,
                          const float* __restrict__ hcat,
                          __nv_bfloat16* __restrict__ obhi, __nv_bfloat16* __restrict__ oblo,
                          int n, int NR)
{
    int node = (blockIdx.x * blockDim.x + threadIdx.x) >> 5;
    if (node >= n) return;
    int lane = threadIdx.x & 31;
    int d0 = lane * 4;
    int head = lane >> 3;

    // 1) convert rel half hcat[node, 0:128] -> bf16 hi/lo cols [0,128)
    float4 base = *(const float4*)(hcat + (long)node * 256 + d0);
    cvt4_store(base, obhi + (long)node * 256 + d0, oblo + (long)node * 256 + d0);

    // 2) GAT gather (atomic-free, unroll x2) -> bf16 hi/lo cols [128,256)
    int e0 = off[NR + node], e1 = off[NR + node + 1];
    float erv = er[node * NH + head];
    float ax0 = 0.f, ay0 = 0.f, az0 = 0.f, aw0 = 0.f, sx0 = 0.f;
    float ax1 = 0.f, ay1 = 0.f, az1 = 0.f, aw1 = 0.f, sx1 = 0.f;
    int j = e0;
    for (; j + 1 < e1; j += 2) {
        int s0 = buf[j], s1 = buf[j + 1];
        float v0 = el[s0 * NH + head] + erv;
        float v1 = el[s1 * NH + head] + erv;
        v0 = (v0 >= 0.f) ? v0 : 0.2f * v0;
        v1 = (v1 >= 0.f) ? v1 : 0.2f * v1;
        float ex0 = __expf(v0), ex1 = __expf(v1);
        float4 z0 = *(const float4*)(z + (long)s0 * 128 + d0);
        float4 z1 = *(const float4*)(z + (long)s1 * 128 + d0);
        sx0 += ex0; sx1 += ex1;
        ax0 = fmaf(ex0, z0.x, ax0); ay0 = fmaf(ex0, z0.y, ay0);
        az0 = fmaf(ex0, z0.z, az0); aw0 = fmaf(ex0, z0.w, aw0);
        ax1 = fmaf(ex1, z1.x, ax1); ay1 = fmaf(ex1, z1.y, ay1);
        az1 = fmaf(ex1, z1.z, az1); aw1 = fmaf(ex1, z1.w, aw1);
    }
    if (j < e1) {
        int s0 = buf[j];
        float v0 = el[s0 * NH + head] + erv;
        v0 = (v0 >= 0.f) ? v0 : 0.2f * v0;
        float ex0 = __expf(v0);
        float4 z0 = *(const float4*)(z + (long)s0 * 128 + d0);
        sx0 += ex0;
        ax0 = fmaf(ex0, z0.x, ax0); ay0 = fmaf(ex0, z0.y, ay0);
        az0 = fmaf(ex0, z0.z, az0); aw0 = fmaf(ex0, z0.w, aw0);
    }
    float sx = sx0 + sx1;
    float inv = (e1 > e0) ? (1.0f / sx) : 0.0f;
    float4 bg = *(const float4*)(bgat + d0);
    float4 o;
    o.x = fmaf(ax0 + ax1, inv, bg.x); o.y = fmaf(ay0 + ay1, inv, bg.y);
    o.z = fmaf(az0 + az1, inv, bg.z); o.w = fmaf(aw0 + aw1, inv, bg.w);
    cvt4_store(o, obhi + (long)node * 256 + 128 + d0, oblo + (long)node * 256 + 128 + d0);
}

// ---------------- misc ------------------------------------------------------------
__global__ void reduce_sum_k(const float* __restrict__ x, float* out, int n) {
    float s = 0.0f;
    for (int i = blockIdx.x * blockDim.x + threadIdx.x; i < n; i += gridDim.x * blockDim.x)
        s += x[i];
#pragma unroll
    for (int o = 16; o > 0; o >>= 1) s += __shfl_xor_sync(0xFFFFFFFFu, s, o);
    __shared__ float ws[8];
    if ((threadIdx.x & 31) == 0) ws[threadIdx.x >> 5] = s;
    __syncthreads();
    if (threadIdx.x < 32) {
        s = (threadIdx.x < (blockDim.x >> 5)) ? ws[threadIdx.x] : 0.0f;
#pragma unroll
        for (int o = 4; o > 0; o >>= 1) s += __shfl_xor_sync(0xFFFFFFFFu, s, o);
        if (threadIdx.x == 0) atomicAdd(out, s);
    }
}

// ---------------- launcher ----------------------------------------------------------
extern "C" void kernel_launch(void* const* d_in, const int* in_sizes, int n_in,
                              void* d_out, int out_size)
{
    const float* feat   = (const float*)d_in[0];
    const int*   src    = (const int*)  d_in[1];
    const int*   dst    = (const int*)  d_in[2];
    const int*   et     = (const int*)  d_in[3];
    const float* tw     = (const float*)d_in[4];
    const float* W_rel  = (const float*)d_in[5];
    const float* b_rel  = (const float*)d_in[6];
    const float* W_loop = (const float*)d_in[7];
    const float* W_gat  = (const float*)d_in[8];
    const float* attn_l = (const float*)d_in[9];
    const float* attn_r = (const float*)d_in[10];
    const float* b_gat  = (const float*)d_in[11];
    const float* W_fuse = (const float*)d_in[12];
    const float* b_fuse = (const float*)d_in[13];
    const float* W_gate = (const float*)d_in[14];
    const float* b_gate = (const float*)d_in[15];

    const int Nn = in_sizes[0] / D;
    const int E  = in_sizes[1];
    const int NR = Nn * R;
    const int NK = NR + Nn;

    cudaFuncSetAttribute(bf_gemm<1>, cudaFuncAttributeMaxDynamicSharedMemorySize, SMEM_STD);
    cudaFuncSetAttribute(bf_gemm<2>, cudaFuncAttributeMaxDynamicSharedMemorySize, SMEM_STD);
    cudaFuncSetAttribute(bf_gemm<3>, cudaFuncAttributeMaxDynamicSharedMemorySize, SMEM_STD);
    cudaFuncSetAttribute(bf_gemm<4>, cudaFuncAttributeMaxDynamicSharedMemorySize, SMEM_STD);
    cudaFuncSetAttribute(bf_gemm<5>, cudaFuncAttributeMaxDynamicSharedMemorySize, SMEM_STD);
    cudaFuncSetAttribute(bf_gemm<7>, cudaFuncAttributeMaxDynamicSharedMemorySize, SMEM_REL);

    float *hcat, *z, *el, *er, *tws;
    int *cnt, *off, *cur, *btot, *buf;
    __nv_bfloat16 *Ahi, *Alo, *Bhi_a, *Blo_a;
    uint32_t *whi, *wlo;
    cudaGetSymbolAddress((void**)&hcat, g_hcat);
    cudaGetSymbolAddress((void**)&z,    g_z);
    cudaGetSymbolAddress((void**)&el,   g_el);
    cudaGetSymbolAddress((void**)&er,   g_er);
    cudaGetSymbolAddress((void**)&tws,  g_twsum);
    cudaGetSymbolAddress((void**)&cnt,  g_cnt);
    cudaGetSymbolAddress((void**)&off,  g_off);
    cudaGetSymbolAddress((void**)&cur,  g_cur);
    cudaGetSymbolAddress((void**)&btot, g_btot);
    cudaGetSymbolAddress((void**)&buf,  g_buf);
    cudaGetSymbolAddress((void**)&Ahi,  g_ahi);
    cudaGetSymbolAddress((void**)&Alo,  g_alo);
    cudaGetSymbolAddress((void**)&Bhi_a, g_bhi);
    cudaGetSymbolAddress((void**)&Blo_a, g_blo);
    cudaGetSymbolAddress((void**)&whi,  g_wpk_hi);
    cudaGetSymbolAddress((void**)&wlo,  g_wpk_lo);

    const int MB = (Nn + 127) / 128;
    const int TPB = 256;
    const int e_blocks      = (E + TPB - 1) / TPB;
    const int nk_blocks     = (NK + TPB - 1) / TPB;
    const int nb            = (NK + 2047) / 2048;
    const int gat_blocks    = (Nn + 7) / 8;
    const int cvt128_blocks = (Nn * D / 4 + TPB - 1) / TPB;

    // CSR build + temporal mean (zero_int also zeroes tw_sum)
    zero_int_k<<<nk_blocks, TPB>>>(cnt, NK, tws);
    reduce_sum_k<<<256, 256>>>(tw, tws, E);
    hist_k<<<e_blocks, TPB>>>(src, dst, et, cnt, E, NR);
    scan1_k<<<nb, 256>>>(cnt, off, btot, NK);
    scan2_k<<<1, 256>>>(btot, nb);
    scan3_k<<<nk_blocks, TPB>>>(off, cur, btot, NK, 2 * E);
    fill_k<<<e_blocks, TPB>>>(src, dst, et, cur, buf, E, NR);

    // all weights in one launch
    cvt_wt_all_k<<<(WPK_ROWS * 128 + TPB - 1) / TPB, TPB>>>(
        W_rel, W_loop, W_gat, W_fuse, W_gate, whi, wlo);

    cvt_act_k<<<cvt128_blocks, TPB>>>(feat, Ahi, Alo, Nn * D / 4);

    __nv_bfloat16 *cur_hi = Ahi, *cur_lo = Alo;
    __nv_bfloat16 *oth_hi = Bhi_a, *oth_lo = Blo_a;

    for (int l = 0; l < NL; l++) {
        const float* brel_l = b_rel  + l * D;
        const float* bgat_l = b_gat  + l * D;
        const float* al_l   = attn_l + l * NH * DH;
        const float* ar_l   = attn_r + l * NH * DH;
        const uint32_t* wrel_hi  = whi + (long)(l * 1024) * 128;
        const uint32_t* wrel_lo  = wlo + (long)(l * 1024) * 128;
        const uint32_t* wloop_hi = whi + (long)(3072 + l * 64) * 128;
        const uint32_t* wloop_lo = wlo + (long)(3072 + l * 64) * 128;

        // 1) dual GEMM: y0 -> hcat[:,0:128] = X@W_loop + b_rel ; y1 -> z + el/er
        bf_gemm<5><<<dim3(MB, 2), 512, SMEM_STD>>>(
            cur_hi, cur_lo, D, wloop_hi, wloop_lo, (long)192 * 128,
            hcat, 2 * D, nullptr, nullptr,
            Nn, D, brel_l,
            z, el, er, al_l, ar_l,
            nullptr, nullptr, nullptr, nullptr, nullptr, nullptr, 0.f);

        // 2) rel GEMM, 2 relations per CTA, fused CSR scatter
        bf_gemm<7><<<dim3(MB, R / 2), 512, SMEM_REL>>>(
            cur_hi, cur_lo, D, wrel_hi, wrel_lo, 64 * 128,
            nullptr, 0, nullptr, nullptr,
            Nn, D, nullptr,
            nullptr, nullptr, nullptr, nullptr, nullptr,
            off, buf, hcat,
            nullptr, nullptr, nullptr, 0.f);

        // 3) GAT gather + fused bf16 conversion of both halves -> oth buffers
        gat_cvt_k<<<gat_blocks, TPB>>>(off, buf, el, er, z, bgat_l, hcat,
                                       oth_hi, oth_lo, Nn, NR);

        // 4) fuse (+ gate at layer 0)
        if (l == 0) {
            bf_gemm<3><<<dim3(MB, 1), 512, SMEM_STD>>>(
                oth_hi, oth_lo, 2 * D, whi + (long)3456 * 128, wlo + (long)3456 * 128, 0,
                z, D, cur_hi, cur_lo,
                Nn, 2 * D, b_fuse,
                nullptr, nullptr, nullptr, nullptr, nullptr,
                nullptr, nullptr, nullptr, nullptr, nullptr, nullptr, 0.f);
            bf_gemm<4><<<dim3(MB, 1), 512, SMEM_STD>>>(
                cur_hi, cur_lo, D, whi + (long)3584 * 128, wlo + (long)3584 * 128, 0,
                nullptr, 0, oth_hi, oth_lo,
                Nn, D, b_gate,
                nullptr, nullptr, nullptr, nullptr, nullptr,
                nullptr, nullptr, nullptr,
                z, W_gate + (long)D * D, tws, 1.0f / (float)E);
            __nv_bfloat16* t;
            t = cur_hi; cur_hi = oth_hi; oth_hi = t;
            t = cur_lo; cur_lo = oth_lo; oth_lo = t;
        } else if (l < NL - 1) {
            bf_gemm<2><<<dim3(MB, 1), 512, SMEM_STD>>>(
                oth_hi, oth_lo, 2 * D, whi + (long)3456 * 128, wlo + (long)3456 * 128, 0,
                nullptr, 0, cur_hi, cur_lo,
                Nn, 2 * D, b_fuse,
                nullptr, nullptr, nullptr, nullptr, nullptr,
                nullptr, nullptr, nullptr, nullptr, nullptr, nullptr, 0.f);
        } else {
            bf_gemm<1><<<dim3(MB, 1), 512, SMEM_STD>>>(
                oth_hi, oth_lo, 2 * D, whi + (long)3456 * 128, wlo + (long)3456 * 128, 0,
                (float*)d_out, D, nullptr, nullptr,
                Nn, 2 * D, b_fuse,
                nullptr, nullptr, nullptr, nullptr, nullptr,
                nullptr, nullptr, nullptr, nullptr, nullptr, nullptr, 0.f);
        }
    }
}

// round 14
// speedup vs baseline: 1.1558x; 1.0567x over previous
#include <cuda_runtime.h>
#include <cuda_bf16.h>
#include <math.h>
#include <stdint.h>

// Problem constants: N=30000, E=480000, D=128, R=16, H=4, DH=32, L=3
#define MAXN 30000
#define MAXE 480000
#define D 128
#define R 16
#define NH 4
#define DH 32
#define NL 3
#define NKMAX (MAXN * (R + 1))

// ---------------- scratch ----------------------------------------------------
__device__ float g_hcat[(long)MAXN * (2 * D)];
__device__ float g_z[(long)MAXN * D];
__device__ float g_el[MAXN * NH];
__device__ float g_er[MAXN * NH];
__device__ float g_twsum;
__device__ int g_cnt[NKMAX];
__device__ int g_off[NKMAX + 1];
__device__ int g_cur[NKMAX];
__device__ int g_btot[512];
__device__ int g_buf[2 * MAXE];
__device__ __nv_bfloat16 g_ahi[(long)MAXN * 256];
__device__ __nv_bfloat16 g_alo[(long)MAXN * 256];
__device__ __nv_bfloat16 g_bhi[(long)MAXN * 256];
__device__ __nv_bfloat16 g_blo[(long)MAXN * 256];
// packed bf16-pair weights (rows of 128 words, column-permuted):
//   [0,3072): W_rel (3 x 16 x 64)  [3072,3264): W_loop (3x64) [3264,3456): W_gat (3x64)
//   [3456,3584): W_fuse            [3584,3648): W_gate
#define WPK_ROWS 3648
__device__ uint32_t g_wpk_hi[WPK_ROWS * 128];
__device__ uint32_t g_wpk_lo[WPK_ROWS * 128];

// ---------------- helpers ----------------------------------------------------
__device__ __forceinline__ void red_add_v4(float* p, float x, float y, float z, float w) {
    asm volatile("red.global.add.v4.f32 [%0], {%1, %2, %3, %4};"
                 :: "l"(p), "f"(x), "f"(y), "f"(z), "f"(w) : "memory");
}
__device__ __forceinline__ void ldsm4(uint32_t r[4], uint32_t addr) {
    asm volatile("ldmatrix.sync.aligned.m8n8.x4.shared.b16 {%0,%1,%2,%3}, [%4];"
                 : "=r"(r[0]), "=r"(r[1]), "=r"(r[2]), "=r"(r[3]) : "r"(addr));
}
__device__ __forceinline__ void mma16816(float c[4], const uint32_t a[4], const uint32_t b[2]) {
    asm volatile("mma.sync.aligned.m16n8k16.row.col.f32.bf16.bf16.f32 "
                 "{%0,%1,%2,%3}, {%4,%5,%6,%7}, {%8,%9}, {%0,%1,%2,%3};"
                 : "+f"(c[0]), "+f"(c[1]), "+f"(c[2]), "+f"(c[3])
                 : "r"(a[0]), "r"(a[1]), "r"(a[2]), "r"(a[3]), "r"(b[0]), "r"(b[1]));
}
__device__ __forceinline__ void cp16(uint32_t dst, const void* src, bool pred) {
    int sz = pred ? 16 : 0;
    asm volatile("cp.async.cg.shared.global [%0], [%1], 16, %2;"
                 :: "r"(dst), "l"(src), "r"(sz));
}
__device__ __forceinline__ void cp_commit() { asm volatile("cp.async.commit_group;"); }
template <int NN> __device__ __forceinline__ void cp_wait() {
    asm volatile("cp.async.wait_group %0;" :: "n"(NN));
}
__device__ __forceinline__ void cvt4_store(float4 v, __nv_bfloat16* hi, __nv_bfloat16* lo) {
    __nv_bfloat162 H0, H1, L0, L1;
    H0.x = __float2bfloat16_rn(v.x); H0.y = __float2bfloat16_rn(v.y);
    H1.x = __float2bfloat16_rn(v.z); H1.y = __float2bfloat16_rn(v.w);
    L0.x = __float2bfloat16_rn(v.x - __bfloat162float(H0.x));
    L0.y = __float2bfloat16_rn(v.y - __bfloat162float(H0.y));
    L1.x = __float2bfloat16_rn(v.z - __bfloat162float(H1.x));
    L1.y = __float2bfloat16_rn(v.w - __bfloat162float(H1.y));
    ((__nv_bfloat162*)hi)[0] = H0; ((__nv_bfloat162*)hi)[1] = H1;
    ((__nv_bfloat162*)lo)[0] = L0; ((__nv_bfloat162*)lo)[1] = L1;
}

// ---------------- conversion kernels ------------------------------------------
__global__ void cvt_act_k(const float* __restrict__ x,
                          __nv_bfloat16* __restrict__ hi, __nv_bfloat16* __restrict__ lo,
                          int total4)
{
    int i = blockIdx.x * blockDim.x + threadIdx.x;
    if (i >= total4) return;
    float4 v = ((const float4*)x)[i];
    cvt4_store(v, hi + i * 4, lo + i * 4);
}

// unified weight conversion (also zeroes tw_sum from one thread)
__global__ void cvt_wt_all_k(const float* __restrict__ W_rel, const float* __restrict__ W_loop,
                             const float* __restrict__ W_gat, const float* __restrict__ W_fuse,
                             const float* __restrict__ W_gate,
                             uint32_t* __restrict__ hi, uint32_t* __restrict__ lo,
                             float* __restrict__ tws)
{
    int i = blockIdx.x * blockDim.x + threadIdx.x;
    if (i == 0) *tws = 0.0f;
    if (i >= WPK_ROWS * 128) return;
    int r = i >> 7, n = i & 127;
    const float* src; int k2;
    if (r < 3072)      { src = W_rel;  k2 = r; }
    else if (r < 3264) { src = W_loop; k2 = r - 3072; }
    else if (r < 3456) { src = W_gat;  k2 = r - 3264; }
    else if (r < 3584) { src = W_fuse; k2 = r - 3456; }
    else               { src = W_gate; k2 = r - 3584; }
    float a = src[(long)(2 * k2) * 128 + n];
    float b = src[(long)(2 * k2 + 1) * 128 + n];
    __nv_bfloat16 ah = __float2bfloat16_rn(a), bh = __float2bfloat16_rn(b);
    __nv_bfloat162 H; H.x = ah; H.y = bh;
    __nv_bfloat162 Lw;
    Lw.x = __float2bfloat16_rn(a - __bfloat162float(ah));
    Lw.y = __float2bfloat16_rn(b - __bfloat162float(bh));
    int np = (n & ~31) | ((n & 7) << 2) | ((n >> 3) & 3);
    hi[(long)r * 128 + np] = *(uint32_t*)&H;
    lo[(long)r * 128 + np] = *(uint32_t*)&Lw;
}

// convert rel half hcat[:,0:128] -> bf16 hi/lo cols [0,128)
__global__ void cvt_rel_k(const float* __restrict__ hcat,
                          __nv_bfloat16* __restrict__ obhi, __nv_bfloat16* __restrict__ oblo,
                          int total32)   // total32 = Nn * 32
{
    int i = blockIdx.x * blockDim.x + threadIdx.x;
    if (i >= total32) return;
    int node = i >> 5, c4 = (i & 31) * 4;
    float4 v = *(const float4*)(hcat + (long)node * 256 + c4);
    cvt4_store(v, obhi + (long)node * 256 + c4, oblo + (long)node * 256 + c4);
}

// ---------------- CSR build ----------------------------------------------------
__global__ void zero_int_k(int* p, int n) {
    int i = blockIdx.x * blockDim.x + threadIdx.x;
    if (i < n) p[i] = 0;
}
__global__ void hist_k(const int* __restrict__ src, const int* __restrict__ dst,
                       const int* __restrict__ et, int* __restrict__ cnt, int E, int NR)
{
    int e = blockIdx.x * blockDim.x + threadIdx.x;
    if (e >= E) return;
    atomicAdd(&cnt[src[e] * R + et[e]], 1);
    atomicAdd(&cnt[NR + dst[e]], 1);
}
__global__ void scan1_k(const int* __restrict__ cnt, int* __restrict__ off,
                        int* __restrict__ btot, int n)
{
    __shared__ int ws[8];
    int t = threadIdx.x;
    int base = blockIdx.x * 2048 + t * 8;
    int v[8], s = 0;
#pragma unroll
    for (int i = 0; i < 8; i++) {
        int x = (base + i < n) ? cnt[base + i] : 0;
        v[i] = s; s += x;
    }
    int lane = t & 31, w = t >> 5;
    int inc = s;
#pragma unroll
    for (int o = 1; o < 32; o <<= 1) {
        int y = __shfl_up_sync(0xFFFFFFFFu, inc, o);
        if (lane >= o) inc += y;
    }
    if (lane == 31) ws[w] = inc;
    int texc = inc - s;
    __syncthreads();
    int wbase = 0;
#pragma unroll
    for (int i = 0; i < 8; i++) wbase += (i < w) ? ws[i] : 0;
#pragma unroll
    for (int i = 0; i < 8; i++)
        if (base + i < n) off[base + i] = wbase + texc + v[i];
    if (t == 255) btot[blockIdx.x] = wbase + inc;
}
__global__ void scan2_k(int* btot, int nb) {
    __shared__ int ws[8];
    int t = threadIdx.x;
    int xv = (t < nb) ? btot[t] : 0;
    int lane = t & 31, w = t >> 5;
    int inc = xv;
#pragma unroll
    for (int o = 1; o < 32; o <<= 1) {
        int y = __shfl_up_sync(0xFFFFFFFFu, inc, o);
        if (lane >= o) inc += y;
    }
    if (lane == 31) ws[w] = inc;
    __syncthreads();
    int wbase = 0;
#pragma unroll
    for (int i = 0; i < 8; i++) wbase += (i < w) ? ws[i] : 0;
    if (t < nb) btot[t] = wbase + inc - xv;
}
__global__ void scan3_k(int* __restrict__ off, int* __restrict__ cur,
                        const int* __restrict__ btot, int n, int total)
{
    int i = blockIdx.x * blockDim.x + threadIdx.x;
    if (i < n) {
        int o = off[i] + btot[i >> 11];
        off[i] = o; cur[i] = o;
    }
    if (i == 0) off[n] = total;
}
__global__ void fill_k(const int* __restrict__ src, const int* __restrict__ dst,
                       const int* __restrict__ et, int* __restrict__ cur,
                       int* __restrict__ buf, int E, int NR)
{
    int e = blockIdx.x * blockDim.x + threadIdx.x;
    if (e >= E) return;
    int s = src[e], d = dst[e];
    int p1 = atomicAdd(&cur[s * R + et[e]], 1);
    buf[p1] = d;
    int p2 = atomicAdd(&cur[NR + d], 1);
    buf[p2] = s;
}

// ---------------- bf16x3 tensor-core GEMM -------------------------------------
// MODE: 1 bias+relu->fp32 | 2 bias+relu->bf16 | 3 bias->fp32+bf16 |
//       4 temporal gate->bf16 | 5 dual (y0 bias->C; y1 z + el/er) |
//       7 rel x2: two relations per CTA, CSR scatter via paired red.v4
#define AS_BUF 8192
#define BS_BUF 8704
#define OFF_AHI 0
#define OFF_ALO (2 * AS_BUF)
#define OFF_B5  (4 * AS_BUF)
#define SMEM_STD (4 * AS_BUF + 4 * BS_BUF)   // 67584
#define SMEM_REL (4 * AS_BUF + 8 * BS_BUF)   // 102400

template <int MODE>
__global__ __launch_bounds__(512)
void bf_gemm(const __nv_bfloat16* __restrict__ Ahi, const __nv_bfloat16* __restrict__ Alo,
             int lda,
             const uint32_t* __restrict__ Bhi, const uint32_t* __restrict__ Blo, long bstr,
             float* __restrict__ C, int ldc,
             __nv_bfloat16* __restrict__ obhi, __nv_bfloat16* __restrict__ oblo,
             int M, int K,
             const float* __restrict__ bias,
             float* __restrict__ zout, float* __restrict__ el, float* __restrict__ er,
             const float* __restrict__ attnl, const float* __restrict__ attnr,
             const int* __restrict__ csr_off, const int* __restrict__ csr_buf,
             float* __restrict__ hcat,
             const float* __restrict__ hcsrc, const float* __restrict__ gate_wlast,
             const float* __restrict__ tw_sum, float invE)
{
    extern __shared__ char sm[];
    const uint32_t smB = (uint32_t)__cvta_generic_to_shared(sm);
    constexpr int NREL = (MODE == 7) ? 2 : 1;

    const uint32_t* BhY = Bhi + (long)blockIdx.y * (NREL * bstr);
    const uint32_t* BlY = Blo + (long)blockIdx.y * (NREL * bstr);

    const int m0   = blockIdx.x * 128;
    const int tid  = threadIdx.x;
    const int lane = tid & 31;
    const int wid  = tid >> 5;
    const int grp  = lane >> 2;
    const int tig  = lane & 3;
    const int wm   = (wid >> 2) * 32;
    const int wn   = (wid & 3) * 32;

    const int aRow = tid >> 2;
    const int aC   = tid & 3;
    const int aSC  = aC ^ ((aRow >> 1) & 3);
    const int gmA  = m0 + aRow;
    const bool aOk = gmA < M;
    const long aSrcOff = (long)(aOk ? gmA : 0) * lda + aC * 8;
    const uint32_t aDst = aRow * 64 + aSC * 16;
    const int bRow = tid >> 5;
    const int bC   = tid & 31;
    const uint32_t bDst = bRow * 544 + bC * 16;
    const int bSrcOff = bRow * 128 + bC * 4;

    auto offB = [&](int b, int rel, int hl) -> uint32_t {
        return OFF_B5 + (uint32_t)(((b * NREL + rel) * 2 + hl) * BS_BUF);
    };
    auto issue = [&](int k0, int b) {
        cp16(smB + OFF_AHI + b * AS_BUF + aDst, Ahi + aSrcOff + k0, aOk);
        cp16(smB + OFF_ALO + b * AS_BUF + aDst, Alo + aSrcOff + k0, aOk);
#pragma unroll
        for (int rel = 0; rel < NREL; rel++) {
            cp16(smB + offB(b, rel, 0) + bDst, BhY + rel * bstr + (k0 >> 1) * 128 + bSrcOff, true);
            cp16(smB + offB(b, rel, 1) + bDst, BlY + rel * bstr + (k0 >> 1) * 128 + bSrcOff, true);
        }
        cp_commit();
    };

    float acc[NREL][2][4][4];
#pragma unroll
    for (int r = 0; r < NREL; r++)
#pragma unroll
        for (int i = 0; i < 2; i++)
#pragma unroll
            for (int j = 0; j < 4; j++)
#pragma unroll
                for (int k = 0; k < 4; k++) acc[r][i][j][k] = 0.f;

    const int arow_l  = wm + (lane & 15);
    const int aShift  = (arow_l >> 1) & 3;
    const int aChunk0 = lane >> 4;
    const uint32_t aRowByte = arow_l * 64;

    const int nch = K >> 5;
    issue(0, 0);

    for (int c = 0; c < nch; c++) {
        const int b = c & 1;
        if (c + 1 < nch) issue((c + 1) << 5, b ^ 1);
        if (c + 1 < nch) cp_wait<1>(); else cp_wait<0>();
        __syncthreads();

#pragma unroll
        for (int kc = 0; kc < 2; kc++) {
            uint32_t ah[2][4], al[2][4];
#pragma unroll
            for (int mt = 0; mt < 2; mt++) {
                const int sc = ((kc * 2 + aChunk0) ^ aShift) * 16;
                uint32_t off = aRowByte + mt * 1024 + sc;
                ldsm4(ah[mt], smB + OFF_AHI + b * AS_BUF + off);
                ldsm4(al[mt], smB + OFF_ALO + b * AS_BUF + off);
            }
            const int r0 = kc * 8 + tig;
            const uint32_t bo0 = (uint32_t)((r0 * 136 + wn + grp * 4) << 2);
            const uint32_t bo1 = (uint32_t)(((r0 + 4) * 136 + wn + grp * 4) << 2);
#pragma unroll
            for (int rel = 0; rel < NREL; rel++) {
                const char* bsH = sm + offB(b, rel, 0);
                const char* bsL = sm + offB(b, rel, 1);
                uint4 h0 = *(const uint4*)(bsH + bo0);
                uint4 h1 = *(const uint4*)(bsH + bo1);
                uint4 l0 = *(const uint4*)(bsL + bo0);
                uint4 l1 = *(const uint4*)(bsL + bo1);
                uint32_t bh[4][2], bl[4][2];
                bh[0][0] = h0.x; bh[1][0] = h0.y; bh[2][0] = h0.z; bh[3][0] = h0.w;
                bh[0][1] = h1.x; bh[1][1] = h1.y; bh[2][1] = h1.z; bh[3][1] = h1.w;
                bl[0][0] = l0.x; bl[1][0] = l0.y; bl[2][0] = l0.z; bl[3][0] = l0.w;
                bl[0][1] = l1.x; bl[1][1] = l1.y; bl[2][1] = l1.z; bl[3][1] = l1.w;
#pragma unroll
                for (int mt = 0; mt < 2; mt++)
#pragma unroll
                    for (int nt = 0; nt < 4; nt++) {
                        mma16816(acc[rel][mt][nt], ah[mt], bh[nt]);
                        mma16816(acc[rel][mt][nt], al[mt], bh[nt]);
                        mma16816(acc[rel][mt][nt], ah[mt], bl[nt]);
                    }
            }
        }
        __syncthreads();
    }

    // ================= epilogues =================
    if (MODE == 7) {
        const int g4   = (tig >> 1) * 4;
        const int ntb  = (tig & 1) * 2;
#pragma unroll
        for (int rel = 0; rel < NREL; rel++) {
            const int rY = blockIdx.y * NREL + rel;
#pragma unroll
            for (int mt = 0; mt < 2; mt++)
#pragma unroll
                for (int half = 0; half < 2; half++) {
                    const int gm = m0 + wm + mt * 16 + grp + half * 8;
                    float q[4][4];
#pragma unroll
                    for (int nt = 0; nt < 4; nt++) {
                        float v0 = acc[rel][mt][nt][half * 2 + 0];
                        float v1 = acc[rel][mt][nt][half * 2 + 1];
                        float o0 = __shfl_xor_sync(0xFFFFFFFFu, v0, 1);
                        float o1 = __shfl_xor_sync(0xFFFFFFFFu, v1, 1);
                        if ((tig & 1) == 0) { q[nt][0] = v0; q[nt][1] = v1; q[nt][2] = o0; q[nt][3] = o1; }
                        else                { q[nt][0] = o0; q[nt][1] = o1; q[nt][2] = v0; q[nt][3] = v1; }
                    }
                    if (gm >= M) continue;
                    const int key = gm * R + rY;
                    const int e0 = csr_off[key], e1 = csr_off[key + 1];
                    for (int e = e0; e < e1; e++) {
                        const int d = csr_buf[e];
                        float* basep = hcat + (long)d * 256 + wn + g4;
                        red_add_v4(basep + ntb * 8,
                                   q[ntb][0], q[ntb][1], q[ntb][2], q[ntb][3]);
                        red_add_v4(basep + (ntb + 1) * 8,
                                   q[ntb + 1][0], q[ntb + 1][1], q[ntb + 1][2], q[ntb + 1][3]);
                    }
                }
        }
        return;
    }

    if (MODE == 5 && blockIdx.y == 1) {
        const int h = wid & 3;
#pragma unroll
        for (int mt = 0; mt < 2; mt++)
#pragma unroll
            for (int half = 0; half < 2; half++) {
                const int gm = m0 + wm + mt * 16 + grp + half * 8;
                const bool ok = gm < M;
                float elp = 0.f, erp = 0.f;
#pragma unroll
                for (int nt = 0; nt < 4; nt++) {
                    const int n = wn + nt * 8 + 2 * tig;
                    float v0 = acc[0][mt][nt][half * 2 + 0];
                    float v1 = acc[0][mt][nt][half * 2 + 1];
                    if (ok) {
                        float2 o; o.x = v0; o.y = v1;
                        *(float2*)(zout + (long)gm * 128 + n) = o;
                    }
                    const int dh = nt * 8 + 2 * tig;
                    elp += v0 * attnl[h * 32 + dh] + v1 * attnl[h * 32 + dh + 1];
                    erp += v0 * attnr[h * 32 + dh] + v1 * attnr[h * 32 + dh + 1];
                }
                elp += __shfl_xor_sync(0xFFFFFFFFu, elp, 1);
                elp += __shfl_xor_sync(0xFFFFFFFFu, elp, 2);
                erp += __shfl_xor_sync(0xFFFFFFFFu, erp, 1);
                erp += __shfl_xor_sync(0xFFFFFFFFu, erp, 2);
                if (ok && tig == 0) {
                    el[gm * NH + h] = elp;
                    er[gm * NH + h] = erp;
                }
            }
        return;
    }

    float twm = 0.0f;
    if (MODE == 4) twm = tw_sum[0] * invE;

#pragma unroll
    for (int mt = 0; mt < 2; mt++)
#pragma unroll
        for (int nt = 0; nt < 4; nt++) {
            const int n = wn + nt * 8 + 2 * tig;
#pragma unroll
            for (int half = 0; half < 2; half++) {
                const int gm = m0 + wm + mt * 16 + grp + half * 8;
                if (gm >= M) continue;
                float v0 = acc[0][mt][nt][half * 2 + 0];
                float v1 = acc[0][mt][nt][half * 2 + 1];
                if (bias) { v0 += bias[n]; v1 += bias[n + 1]; }
                if (MODE == 1 || MODE == 2) { v0 = fmaxf(v0, 0.f); v1 = fmaxf(v1, 0.f); }
                if (MODE == 4) {
                    float g0 = v0 + twm * gate_wlast[n];
                    float g1 = v1 + twm * gate_wlast[n + 1];
                    g0 = 1.0f / (1.0f + expf(-g0));
                    g1 = 1.0f / (1.0f + expf(-g1));
                    float2 hc = *(const float2*)(hcsrc + (long)gm * 128 + n);
                    v0 = fmaxf(hc.x * g0, 0.f);
                    v1 = fmaxf(hc.y * g1, 0.f);
                }
                if (MODE == 1 || MODE == 3 || MODE == 5) {
                    float2 o; o.x = v0; o.y = v1;
                    *(float2*)(C + (long)gm * ldc + n) = o;
                }
                if (MODE == 2 || MODE == 3 || MODE == 4) {
                    __nv_bfloat162 H, Lw;
                    H.x = __float2bfloat16_rn(v0);
                    H.y = __float2bfloat16_rn(v1);
                    Lw.x = __float2bfloat16_rn(v0 - __bfloat162float(H.x));
                    Lw.y = __float2bfloat16_rn(v1 - __bfloat162float(H.y));
                    *(__nv_bfloat162*)(obhi + (long)gm * 128 + n) = H;
                    *(__nv_bfloat162*)(oblo + (long)gm * 128 + n) = Lw;
                }
            }
        }
}

// ---------------- GAT gather -> bf16 gat half (runs concurrent with rel GEMM) -----
__global__ void gat_only_k(const int* __restrict__ off, const int* __restrict__ buf,
                           const float* __restrict__ el, const float* __restrict__ er,
                           const float* __restrict__ z, const float* __restrict__ bgat,
                           __nv_bfloat16* __restrict__ obhi, __nv_bfloat16* __restrict__ oblo,
                           int n, int NR)
{
    int node = (blockIdx.x * blockDim.x + threadIdx.x) >> 5;
    if (node >= n) return;
    int lane = threadIdx.x & 31;
    int d0 = lane * 4;
    int head = lane >> 3;

    int e0 = off[NR + node], e1 = off[NR + node + 1];
    float erv = er[node * NH + head];
    float ax0 = 0.f, ay0 = 0.f, az0 = 0.f, aw0 = 0.f, sx0 = 0.f;
    float ax1 = 0.f, ay1 = 0.f, az1 = 0.f, aw1 = 0.f, sx1 = 0.f;
    int j = e0;
    for (; j + 1 < e1; j += 2) {
        int s0 = buf[j], s1 = buf[j + 1];
        float v0 = el[s0 * NH + head] + erv;
        float v1 = el[s1 * NH + head] + erv;
        v0 = (v0 >= 0.f) ? v0 : 0.2f * v0;
        v1 = (v1 >= 0.f) ? v1 : 0.2f * v1;
        float ex0 = __expf(v0), ex1 = __expf(v1);
        float4 z0 = *(const float4*)(z + (long)s0 * 128 + d0);
        float4 z1 = *(const float4*)(z + (long)s1 * 128 + d0);
        sx0 += ex0; sx1 += ex1;
        ax0 = fmaf(ex0, z0.x, ax0); ay0 = fmaf(ex0, z0.y, ay0);
        az0 = fmaf(ex0, z0.z, az0); aw0 = fmaf(ex0, z0.w, aw0);
        ax1 = fmaf(ex1, z1.x, ax1); ay1 = fmaf(ex1, z1.y, ay1);
        az1 = fmaf(ex1, z1.z, az1); aw1 = fmaf(ex1, z1.w, aw1);
    }
    if (j < e1) {
        int s0 = buf[j];
        float v0 = el[s0 * NH + head] + erv;
        v0 = (v0 >= 0.f) ? v0 : 0.2f * v0;
        float ex0 = __expf(v0);
        float4 z0 = *(const float4*)(z + (long)s0 * 128 + d0);
        sx0 += ex0;
        ax0 = fmaf(ex0, z0.x, ax0); ay0 = fmaf(ex0, z0.y, ay0);
        az0 = fmaf(ex0, z0.z, az0); aw0 = fmaf(ex0, z0.w, aw0);
    }
    float sx = sx0 + sx1;
    float inv = (e1 > e0) ? (1.0f / sx) : 0.0f;
    float4 bg = *(const float4*)(bgat + d0);
    float4 o;
    o.x = fmaf(ax0 + ax1, inv, bg.x); o.y = fmaf(ay0 + ay1, inv, bg.y);
    o.z = fmaf(az0 + az1, inv, bg.z); o.w = fmaf(aw0 + aw1, inv, bg.w);
    cvt4_store(o, obhi + (long)node * 256 + 128 + d0, oblo + (long)node * 256 + 128 + d0);
}

// ---------------- misc ------------------------------------------------------------
__global__ void reduce_sum_k(const float* __restrict__ x, float* out, int n) {
    float s = 0.0f;
    for (int i = blockIdx.x * blockDim.x + threadIdx.x; i < n; i += gridDim.x * blockDim.x)
        s += x[i];
#pragma unroll
    for (int o = 16; o > 0; o >>= 1) s += __shfl_xor_sync(0xFFFFFFFFu, s, o);
    __shared__ float ws[8];
    if ((threadIdx.x & 31) == 0) ws[threadIdx.x >> 5] = s;
    __syncthreads();
    if (threadIdx.x < 32) {
        s = (threadIdx.x < (blockDim.x >> 5)) ? ws[threadIdx.x] : 0.0f;
#pragma unroll
        for (int o = 4; o > 0; o >>= 1) s += __shfl_xor_sync(0xFFFFFFFFu, s, o);
        if (threadIdx.x == 0) atomicAdd(out, s);
    }
}

// ---------------- launcher ----------------------------------------------------------
extern "C" void kernel_launch(void* const* d_in, const int* in_sizes, int n_in,
                              void* d_out, int out_size)
{
    const float* feat   = (const float*)d_in[0];
    const int*   src    = (const int*)  d_in[1];
    const int*   dst    = (const int*)  d_in[2];
    const int*   et     = (const int*)  d_in[3];
    const float* tw     = (const float*)d_in[4];
    const float* W_rel  = (const float*)d_in[5];
    const float* b_rel  = (const float*)d_in[6];
    const float* W_loop = (const float*)d_in[7];
    const float* W_gat  = (const float*)d_in[8];
    const float* attn_l = (const float*)d_in[9];
    const float* attn_r = (const float*)d_in[10];
    const float* b_gat  = (const float*)d_in[11];
    const float* W_fuse = (const float*)d_in[12];
    const float* b_fuse = (const float*)d_in[13];
    const float* W_gate = (const float*)d_in[14];
    const float* b_gate = (const float*)d_in[15];

    const int Nn = in_sizes[0] / D;
    const int E  = in_sizes[1];
    const int NR = Nn * R;
    const int NK = NR + Nn;

    cudaFuncSetAttribute(bf_gemm<1>, cudaFuncAttributeMaxDynamicSharedMemorySize, SMEM_STD);
    cudaFuncSetAttribute(bf_gemm<2>, cudaFuncAttributeMaxDynamicSharedMemorySize, SMEM_STD);
    cudaFuncSetAttribute(bf_gemm<3>, cudaFuncAttributeMaxDynamicSharedMemorySize, SMEM_STD);
    cudaFuncSetAttribute(bf_gemm<4>, cudaFuncAttributeMaxDynamicSharedMemorySize, SMEM_STD);
    cudaFuncSetAttribute(bf_gemm<5>, cudaFuncAttributeMaxDynamicSharedMemorySize, SMEM_STD);
    cudaFuncSetAttribute(bf_gemm<7>, cudaFuncAttributeMaxDynamicSharedMemorySize, SMEM_REL);

    // lazily-created side stream + events (host objects, created once on the
    // uncaptured correctness call; reused under graph capture as fork/join)
    static cudaStream_t s1 = nullptr;
    static cudaEvent_t evA = nullptr, evB = nullptr, evC = nullptr;
    if (!s1) {
        cudaStreamCreateWithFlags(&s1, cudaStreamNonBlocking);
        cudaEventCreateWithFlags(&evA, cudaEventDisableTiming);
        cudaEventCreateWithFlags(&evB, cudaEventDisableTiming);
        cudaEventCreateWithFlags(&evC, cudaEventDisableTiming);
    }

    float *hcat, *z, *el, *er, *tws;
    int *cnt, *off, *cur, *btot, *buf;
    __nv_bfloat16 *Ahi, *Alo, *Bhi_a, *Blo_a;
    uint32_t *whi, *wlo;
    cudaGetSymbolAddress((void**)&hcat, g_hcat);
    cudaGetSymbolAddress((void**)&z,    g_z);
    cudaGetSymbolAddress((void**)&el,   g_el);
    cudaGetSymbolAddress((void**)&er,   g_er);
    cudaGetSymbolAddress((void**)&tws,  g_twsum);
    cudaGetSymbolAddress((void**)&cnt,  g_cnt);
    cudaGetSymbolAddress((void**)&off,  g_off);
    cudaGetSymbolAddress((void**)&cur,  g_cur);
    cudaGetSymbolAddress((void**)&btot, g_btot);
    cudaGetSymbolAddress((void**)&buf,  g_buf);
    cudaGetSymbolAddress((void**)&Ahi,  g_ahi);
    cudaGetSymbolAddress((void**)&Alo,  g_alo);
    cudaGetSymbolAddress((void**)&Bhi_a, g_bhi);
    cudaGetSymbolAddress((void**)&Blo_a, g_blo);
    cudaGetSymbolAddress((void**)&whi,  g_wpk_hi);
    cudaGetSymbolAddress((void**)&wlo,  g_wpk_lo);

    const int MB = (Nn + 127) / 128;
    const int TPB = 256;
    const int e_blocks      = (E + TPB - 1) / TPB;
    const int nk_blocks     = (NK + TPB - 1) / TPB;
    const int nb            = (NK + 2047) / 2048;
    const int gat_blocks    = (Nn + 7) / 8;
    const int cvt128_blocks = (Nn * D / 4 + TPB - 1) / TPB;
    const int cvtrel_blocks = (Nn * 32 + TPB - 1) / TPB;

    // ---- fork: CSR build on s1, weight/act conversion on main stream ----
    cudaEventRecord(evA, 0);
    cudaStreamWaitEvent(s1, evA, 0);

    zero_int_k<<<nk_blocks, TPB, 0, s1>>>(cnt, NK);
    hist_k<<<e_blocks, TPB, 0, s1>>>(src, dst, et, cnt, E, NR);
    scan1_k<<<nb, 256, 0, s1>>>(cnt, off, btot, NK);
    scan2_k<<<1, 256, 0, s1>>>(btot, nb);
    scan3_k<<<nk_blocks, TPB, 0, s1>>>(off, cur, btot, NK, 2 * E);
    fill_k<<<e_blocks, TPB, 0, s1>>>(src, dst, et, cur, buf, E, NR);
    cudaEventRecord(evC, s1);     // CSR done

    cvt_wt_all_k<<<(WPK_ROWS * 128 + TPB - 1) / TPB, TPB>>>(
        W_rel, W_loop, W_gat, W_fuse, W_gate, whi, wlo, tws);
    reduce_sum_k<<<256, 256>>>(tw, tws, E);
    cvt_act_k<<<cvt128_blocks, TPB>>>(feat, Ahi, Alo, Nn * D / 4);

    __nv_bfloat16 *cur_hi = Ahi, *cur_lo = Alo;
    __nv_bfloat16 *oth_hi = Bhi_a, *oth_lo = Blo_a;

    for (int l = 0; l < NL; l++) {
        const float* brel_l = b_rel  + l * D;
        const float* bgat_l = b_gat  + l * D;
        const float* al_l   = attn_l + l * NH * DH;
        const float* ar_l   = attn_r + l * NH * DH;
        const uint32_t* wrel_hi  = whi + (long)(l * 1024) * 128;
        const uint32_t* wrel_lo  = wlo + (long)(l * 1024) * 128;
        const uint32_t* wloop_hi = whi + (long)(3072 + l * 64) * 128;
        const uint32_t* wloop_lo = wlo + (long)(3072 + l * 64) * 128;

        // 1) dual GEMM (main): y0 -> hcat[:,0:128] = X@W_loop + b_rel ; y1 -> z + el/er
        bf_gemm<5><<<dim3(MB, 2), 512, SMEM_STD>>>(
            cur_hi, cur_lo, D, wloop_hi, wloop_lo, (long)192 * 128,
            hcat, 2 * D, nullptr, nullptr,
            Nn, D, brel_l,
            z, el, er, al_l, ar_l,
            nullptr, nullptr, nullptr, nullptr, nullptr, nullptr, 0.f);

        if (l == 0) cudaStreamWaitEvent(0, evC, 0);  // CSR ready before first rel

        // fork gat onto s1 (needs dual outputs + CSR; runs concurrent with rel)
        cudaEventRecord(evA, 0);
        cudaStreamWaitEvent(s1, evA, 0);

        // 2) rel GEMM (main), 2 relations per CTA, fused CSR scatter into hcat[:,0:128]
        bf_gemm<7><<<dim3(MB, R / 2), 512, SMEM_REL>>>(
            cur_hi, cur_lo, D, wrel_hi, wrel_lo, 64 * 128,
            nullptr, 0, nullptr, nullptr,
            Nn, D, nullptr,
            nullptr, nullptr, nullptr, nullptr, nullptr,
            off, buf, hcat,
            nullptr, nullptr, nullptr, 0.f);

        // 3) gat gather (s1) -> bf16 gat half of oth buffers (disjoint from rel writes)
        gat_only_k<<<gat_blocks, TPB, 0, s1>>>(off, buf, el, er, z, bgat_l,
                                               oth_hi, oth_lo, Nn, NR);
        cudaEventRecord(evB, s1);

        // 4) convert rel half (main, after rel) + join gat
        cvt_rel_k<<<cvtrel_blocks, TPB>>>(hcat, oth_hi, oth_lo, Nn * 32);
        cudaStreamWaitEvent(0, evB, 0);

        // 5) fuse (+ gate at layer 0)
        if (l == 0) {
            bf_gemm<3><<<dim3(MB, 1), 512, SMEM_STD>>>(
                oth_hi, oth_lo, 2 * D, whi + (long)3456 * 128, wlo + (long)3456 * 128, 0,
                z, D, cur_hi, cur_lo,
                Nn, 2 * D, b_fuse,
                nullptr, nullptr, nullptr, nullptr, nullptr,
                nullptr, nullptr, nullptr, nullptr, nullptr, nullptr, 0.f);
            bf_gemm<4><<<dim3(MB, 1), 512, SMEM_STD>>>(
                cur_hi, cur_lo, D, whi + (long)3584 * 128, wlo + (long)3584 * 128, 0,
                nullptr, 0, oth_hi, oth_lo,
                Nn, D, b_gate,
                nullptr, nullptr, nullptr, nullptr, nullptr,
                nullptr, nullptr, nullptr,
                z, W_gate + (long)D * D, tws, 1.0f / (float)E);
            __nv_bfloat16* t;
            t = cur_hi; cur_hi = oth_hi; oth_hi = t;
            t = cur_lo; cur_lo = oth_lo; oth_lo = t;
        } else if (l < NL - 1) {
            bf_gemm<2><<<dim3(MB, 1), 512, SMEM_STD>>>(
                oth_hi, oth_lo, 2 * D, whi + (long)3456 * 128, wlo + (long)3456 * 128, 0,
                nullptr, 0, cur_hi, cur_lo,
                Nn, 2 * D, b_fuse,
                nullptr, nullptr, nullptr, nullptr, nullptr,
                nullptr, nullptr, nullptr, nullptr, nullptr, nullptr, 0.f);
        } else {
            bf_gemm<1><<<dim3(MB, 1), 512, SMEM_STD>>>(
                oth_hi, oth_lo, 2 * D, whi + (long)3456 * 128, wlo + (long)3456 * 128, 0,
                (float*)d_out, D, nullptr, nullptr,
                Nn, 2 * D, b_fuse,
                nullptr, nullptr, nullptr, nullptr, nullptr,
                nullptr, nullptr, nullptr, nullptr, nullptr, nullptr, 0.f);
        }
    }
}